// round 9
// baseline (speedup 1.0000x reference)
#include <cuda_runtime.h>
#include <cstdint>

// ---------------------------------------------------------------------------
// B=16, C=512, S=1024, HEAD=8, D_K=64
// heads view: token n -> channel n>>1, feature j=h*64+d -> spatial ((n&1)<<9)+j
// 3xBF16 compensated: x = hi + lo (bf16), A*B ~= Ah*Bh + Al*Bh + Ah*Bl
// ALL operands pre-split once into bf16 hi/lo global arrays; hot loops do no
// conversions. Legacy mma.sync m16n8k16 (tcgen05 unavailable: harness targets
// sm_103 without the 'a' suffix).
// ---------------------------------------------------------------------------
#define BATCH   16
#define CH      512
#define SP      1024
#define PER_B   (CH*SP)
#define WORDS_B (PER_B/2)       // bf16-pair words per batch image
#define PAIRS_B (256*1024)      // k-pair-packed words per batch

// scratch (device globals)
__device__ unsigned g_wwh[4*512*256], g_wwl[4*512*256];     // Wq,Wk,Wv,Wo bf16 pairs along k
__device__ unsigned g_xph[BATCH*PAIRS_B], g_xpl[BATCH*PAIRS_B];
__device__ unsigned g_qwh[BATCH*WORDS_B], g_qwl[BATCH*WORDS_B];
__device__ unsigned g_kwh[BATCH*WORDS_B], g_kwl[BATCH*WORDS_B];
__device__ unsigned g_vwh[BATCH*WORDS_B], g_vwl[BATCH*WORDS_B];
__device__ unsigned g_aph[BATCH*PAIRS_B], g_apl[BATCH*PAIRS_B];
__device__ float    g_o1[BATCH*PER_B];
__device__ unsigned g_oph[BATCH*PAIRS_B], g_opl[BATCH*PAIRS_B];

__device__ __forceinline__ unsigned packbf(float a, float b) {
    unsigned r;
    asm("cvt.rn.bf16x2.f32 %0, %1, %2;" : "=r"(r) : "f"(b), "f"(a));
    return r;
}
__device__ __forceinline__ void split2(float a, float b, unsigned& hi, unsigned& lo) {
    hi = packbf(a, b);
    float ha = __uint_as_float(hi << 16);
    float hb = __uint_as_float(hi & 0xffff0000u);
    lo = packbf(a - ha, b - hb);
}
__device__ __forceinline__ unsigned prmtb(unsigned a, unsigned b, unsigned sel) {
    unsigned d;
    asm("prmt.b32 %0,%1,%2,%3;" : "=r"(d) : "r"(a), "r"(b), "r"(sel));
    return d;
}
__device__ __forceinline__ void mma16(float* c, const unsigned* a, unsigned b0, unsigned b1) {
    asm volatile(
        "mma.sync.aligned.m16n8k16.row.col.f32.bf16.bf16.f32 "
        "{%0,%1,%2,%3},{%4,%5,%6,%7},{%8,%9},{%0,%1,%2,%3};"
        : "+f"(c[0]), "+f"(c[1]), "+f"(c[2]), "+f"(c[3])
        : "r"(a[0]), "r"(a[1]), "r"(a[2]), "r"(a[3]), "r"(b0), "r"(b1));
}

// ------------------------------ prepasses ---------------------------------
__global__ __launch_bounds__(256)
void wsplit_kernel(const float* __restrict__ Wq, const float* __restrict__ Wk,
                   const float* __restrict__ Wv, const float* __restrict__ Wo)
{
    unsigned w = blockIdx.x * 256 + threadIdx.x;     // word idx, 524288 total
    unsigned m = w >> 17, rem = w & 131071;
    const float* src = m == 0 ? Wq : (m == 1 ? Wk : (m == 2 ? Wv : Wo));
    float2 v = reinterpret_cast<const float2*>(src)[rem];
    unsigned h, l;
    split2(v.x, v.y, h, l);
    g_wwh[w] = h; g_wwl[w] = l;
}

__global__ __launch_bounds__(256)
void xsplit_kernel(const float* __restrict__ X)
{
    unsigned f = blockIdx.x * 256 + threadIdx.x;     // uint4 item, 1048576 total
    unsigned b = f >> 16;
    unsigned kp = (f >> 8) & 255;
    unsigned n4 = (f & 255) << 2;
    const float* p = X + (size_t)b * PER_B + (size_t)(2 * kp) * SP + n4;
    float4 a = *reinterpret_cast<const float4*>(p);
    float4 c = *reinterpret_cast<const float4*>(p + SP);
    uint4 h, l;
    split2(a.x, c.x, h.x, l.x); split2(a.y, c.y, h.y, l.y);
    split2(a.z, c.z, h.z, l.z); split2(a.w, c.w, h.w, l.w);
    size_t o = (size_t)b * PAIRS_B + (size_t)kp * 1024 + n4;
    *reinterpret_cast<uint4*>(g_xph + o) = h;
    *reinterpret_cast<uint4*>(g_xpl + o) = l;
}

// ------------------------------ GEMM core ---------------------------------
// acc = W[128xK] @ B[Kx128] using pre-split pair words.
// smem: Ahp/Alp[128][20], Bph/Bpl[16][132] = 37376 B
#define GEMM_SMEM ((2*128*20 + 2*16*132) * 4)

__device__ __forceinline__ void gemm_acc(
    const unsigned* __restrict__ awh, const unsigned* __restrict__ awl,
    const unsigned* __restrict__ bph, const unsigned* __restrict__ bpl,
    int m0, int n0, unsigned* gsm, float acc[2][8][4])
{
    unsigned (*Ahp)[20]  = reinterpret_cast<unsigned(*)[20]>(gsm);
    unsigned (*Alp)[20]  = reinterpret_cast<unsigned(*)[20]>(gsm + 128*20);
    unsigned (*Bph)[132] = reinterpret_cast<unsigned(*)[132]>(gsm + 2*128*20);
    unsigned (*Bpl)[132] = reinterpret_cast<unsigned(*)[132]>(gsm + 2*128*20 + 16*132);

    const int tid = threadIdx.x, lane = tid & 31, warp = tid >> 5;
    const int wm = warp & 3, wn = warp >> 2;
    const int g = lane >> 2, tg = lane & 3;

#pragma unroll
    for (int mt = 0; mt < 2; mt++)
#pragma unroll
        for (int nt = 0; nt < 8; nt++)
#pragma unroll
            for (int i = 0; i < 4; i++) acc[mt][nt][i] = 0.f;

    for (int kp0 = 0; kp0 < 256; kp0 += 16) {
#pragma unroll
        for (int i = 0; i < 4; i++) {
            int f = tid + i * 256;
            int r = f >> 3, u = (f & 7) << 1;
            size_t src = (size_t)(m0 + r) * 256 + kp0 + u;
            *reinterpret_cast<uint2*>(&Ahp[r][u]) = *reinterpret_cast<const uint2*>(awh + src);
            *reinterpret_cast<uint2*>(&Alp[r][u]) = *reinterpret_cast<const uint2*>(awl + src);
        }
#pragma unroll
        for (int i = 0; i < 2; i++) {
            int f = tid + i * 256;
            int kp = f >> 5, n4 = (f & 31) << 2;
            size_t src = (size_t)(kp0 + kp) * 1024 + n0 + n4;
            *reinterpret_cast<uint4*>(&Bph[kp][n4]) = *reinterpret_cast<const uint4*>(bph + src);
            *reinterpret_cast<uint4*>(&Bpl[kp][n4]) = *reinterpret_cast<const uint4*>(bpl + src);
        }
        __syncthreads();

#pragma unroll
        for (int kc = 0; kc < 2; kc++) {
            const int base = kc * 8;
            unsigned ah[2][4], al[2][4];
#pragma unroll
            for (int mt = 0; mt < 2; mt++) {
                int rm = wm * 32 + mt * 16;
                ah[mt][0] = Ahp[rm + g][base + tg];
                ah[mt][1] = Ahp[rm + g + 8][base + tg];
                ah[mt][2] = Ahp[rm + g][base + tg + 4];
                ah[mt][3] = Ahp[rm + g + 8][base + tg + 4];
                al[mt][0] = Alp[rm + g][base + tg];
                al[mt][1] = Alp[rm + g + 8][base + tg];
                al[mt][2] = Alp[rm + g][base + tg + 4];
                al[mt][3] = Alp[rm + g + 8][base + tg + 4];
            }
#pragma unroll
            for (int ntc = 0; ntc < 2; ntc++) {
                unsigned bh0[4], bh1[4], bl0[4], bl1[4];
#pragma unroll
                for (int j = 0; j < 4; j++) {
                    int cn = wn * 64 + (ntc * 4 + j) * 8;
                    bh0[j] = Bph[base + tg][cn + g];
                    bh1[j] = Bph[base + tg + 4][cn + g];
                    bl0[j] = Bpl[base + tg][cn + g];
                    bl1[j] = Bpl[base + tg + 4][cn + g];
                }
#pragma unroll
                for (int j = 0; j < 4; j++) {
                    mma16(acc[0][ntc * 4 + j], ah[0], bh0[j], bh1[j]);
                    mma16(acc[1][ntc * 4 + j], ah[1], bh0[j], bh1[j]);
                }
#pragma unroll
                for (int j = 0; j < 4; j++) {
                    mma16(acc[0][ntc * 4 + j], al[0], bh0[j], bh1[j]);
                    mma16(acc[1][ntc * 4 + j], al[1], bh0[j], bh1[j]);
                }
#pragma unroll
                for (int j = 0; j < 4; j++) {
                    mma16(acc[0][ntc * 4 + j], ah[0], bl0[j], bl1[j]);
                    mma16(acc[1][ntc * 4 + j], ah[1], bl0[j], bl1[j]);
                }
            }
        }
        __syncthreads();
    }
}

// fused QKV: grid (8, 12, 16); y>>2 selects {Q,K,V}; writes split bf16 images
__global__ __launch_bounds__(256, 2)
void qkv_kernel(const float* __restrict__ bq, const float* __restrict__ bk,
                const float* __restrict__ bv)
{
    extern __shared__ unsigned gsm[];
    const int sel = blockIdx.y >> 2;
    const int m0 = (blockIdx.y & 3) * 128;
    const int n0 = blockIdx.x * 128;
    const int b  = blockIdx.z;
    const unsigned* awh = g_wwh + sel * 131072;
    const unsigned* awl = g_wwl + sel * 131072;
    const unsigned* bph = g_xph + (size_t)b * PAIRS_B;
    const unsigned* bpl = g_xpl + (size_t)b * PAIRS_B;
    const float* bias = sel == 0 ? bq : (sel == 1 ? bk : bv);
    unsigned* oh = (sel == 0 ? g_qwh : (sel == 1 ? g_kwh : g_vwh)) + (size_t)b * WORDS_B;
    unsigned* ol = (sel == 0 ? g_qwl : (sel == 1 ? g_kwl : g_vwl)) + (size_t)b * WORDS_B;

    float acc[2][8][4];
    gemm_acc(awh, awl, bph, bpl, m0, n0, gsm, acc);

    const int tid = threadIdx.x, lane = tid & 31, warp = tid >> 5;
    const int wm = warp & 3, wn = warp >> 2;
    const int g = lane >> 2, tg = lane & 3;
#pragma unroll
    for (int mt = 0; mt < 2; mt++) {
        int r0 = m0 + wm * 32 + mt * 16 + g;
        float bi0 = bias[r0], bi1 = bias[r0 + 8];
#pragma unroll
        for (int nt = 0; nt < 8; nt++) {
            int cn = n0 + wn * 64 + nt * 8 + 2 * tg;
            unsigned h, l;
            split2(acc[mt][nt][0] + bi0, acc[mt][nt][1] + bi0, h, l);
            oh[(size_t)r0 * 512 + (cn >> 1)] = h;
            ol[(size_t)r0 * 512 + (cn >> 1)] = l;
            split2(acc[mt][nt][2] + bi1, acc[mt][nt][3] + bi1, h, l);
            oh[(size_t)(r0 + 8) * 512 + (cn >> 1)] = h;
            ol[(size_t)(r0 + 8) * 512 + (cn >> 1)] = l;
        }
    }
}

// O-conv GEMM: pre-split A (Wo) and pair-packed B; float output
__global__ __launch_bounds__(256, 2)
void gemm_f_kernel(const unsigned* __restrict__ awh, const unsigned* __restrict__ awl,
                   const float* __restrict__ bias,
                   const unsigned* __restrict__ bph_all, const unsigned* __restrict__ bpl_all,
                   float* __restrict__ Y)
{
    extern __shared__ unsigned gsm[];
    const int m0 = blockIdx.y * 128, n0 = blockIdx.x * 128, b = blockIdx.z;
    const unsigned* bph = bph_all + (size_t)b * PAIRS_B;
    const unsigned* bpl = bpl_all + (size_t)b * PAIRS_B;
    float* Yb = Y + (size_t)b * PER_B;

    float acc[2][8][4];
    gemm_acc(awh, awl, bph, bpl, m0, n0, gsm, acc);

    const int tid = threadIdx.x, lane = tid & 31, warp = tid >> 5;
    const int wm = warp & 3, wn = warp >> 2;
    const int g = lane >> 2, tg = lane & 3;
#pragma unroll
    for (int mt = 0; mt < 2; mt++) {
        int r0 = m0 + wm * 32 + mt * 16 + g;
        float bi0 = bias[r0], bi1 = bias[r0 + 8];
#pragma unroll
        for (int nt = 0; nt < 8; nt++) {
            int cn = n0 + wn * 64 + nt * 8 + 2 * tg;
            Yb[(size_t)r0 * SP + cn]           = acc[mt][nt][0] + bi0;
            Yb[(size_t)r0 * SP + cn + 1]       = acc[mt][nt][1] + bi0;
            Yb[(size_t)(r0 + 8) * SP + cn]     = acc[mt][nt][2] + bi1;
            Yb[(size_t)(r0 + 8) * SP + cn + 1] = acc[mt][nt][3] + bi1;
        }
    }
}

// ------------------------------ attention ---------------------------------
// grid (16 qblocks of 64 rows, 8 heads, 16 batch), 128 thr, 2 CTAs/SM.
// smem: Kph/Kpl[128][36] + Vph/Vpl[64][72] = 73728 B
#define ATTN_SMEM ((2*128*36 + 2*64*72) * 4)

__device__ __forceinline__ size_t tok_off(int n, int hoff) {
    return (size_t)(n >> 1) * SP + ((n & 1) << 9) + hoff;
}

__global__ __launch_bounds__(128, 2)
void attn_kernel()
{
    extern __shared__ unsigned smem_u[];
    unsigned (*Kph)[36] = reinterpret_cast<unsigned(*)[36]>(smem_u);
    unsigned (*Kpl)[36] = reinterpret_cast<unsigned(*)[36]>(smem_u + 128*36);
    unsigned (*Vph)[72] = reinterpret_cast<unsigned(*)[72]>(smem_u + 2*128*36);
    unsigned (*Vpl)[72] = reinterpret_cast<unsigned(*)[72]>(smem_u + 2*128*36 + 64*72);

    const int tid = threadIdx.x, lane = tid & 31, warp = tid >> 5;
    const int g = lane >> 2, tg = lane & 3;

    const int b = blockIdx.z, h = blockIdx.y;
    const int n0 = blockIdx.x * 64;
    const size_t bbw = (size_t)b * WORDS_B;
    const int hoff = h * 64;

    // Q fragments (unscaled; 1/8 folded into softmax)
    const int r0l = warp * 16 + g, r1l = r0l + 8;
    const size_t w0 = bbw + (tok_off(n0 + r0l, hoff) >> 1);
    const size_t w1 = bbw + (tok_off(n0 + r1l, hoff) >> 1);
    unsigned qh[4][4], ql[4][4];
#pragma unroll
    for (int kc = 0; kc < 4; kc++) {
        qh[kc][0] = g_qwh[w0 + kc * 8 + tg];
        qh[kc][1] = g_qwh[w1 + kc * 8 + tg];
        qh[kc][2] = g_qwh[w0 + kc * 8 + tg + 4];
        qh[kc][3] = g_qwh[w1 + kc * 8 + tg + 4];
        ql[kc][0] = g_qwl[w0 + kc * 8 + tg];
        ql[kc][1] = g_qwl[w1 + kc * 8 + tg];
        ql[kc][2] = g_qwl[w0 + kc * 8 + tg + 4];
        ql[kc][3] = g_qwl[w1 + kc * 8 + tg + 4];
    }

    float mr0 = -1e30f, mr1 = -1e30f, l0 = 0.f, l1 = 0.f;
    float oa[8][4];
#pragma unroll
    for (int dt = 0; dt < 8; dt++)
#pragma unroll
        for (int i = 0; i < 4; i++) oa[dt][i] = 0.f;

    for (int kb = 0; kb < 8; kb++) {
        // K tile: 128 rows x 8 uint4 (pairs along d)
#pragma unroll
        for (int i = 0; i < 8; i++) {
            int f = tid + i * 128;
            int r = f >> 3, q4 = (f & 7) << 2;
            size_t kw = bbw + (tok_off(kb * 128 + r, hoff) >> 1) + q4;
            *reinterpret_cast<uint4*>(&Kph[r][q4]) = *reinterpret_cast<const uint4*>(g_kwh + kw);
            *reinterpret_cast<uint4*>(&Kpl[r][q4]) = *reinterpret_cast<const uint4*>(g_kwl + kw);
        }
        // V tile: pairs along key via prmt; 64 pair-rows x 8 groups
#pragma unroll
        for (int i = 0; i < 4; i++) {
            int f = tid + i * 128;
            int pr = f >> 3, q = f & 7;
            size_t vw = bbw + (size_t)(kb * 64 + pr) * 512 + (hoff >> 1) + q * 4;
            uint4 a = *reinterpret_cast<const uint4*>(g_vwh + vw);
            uint4 c = *reinterpret_cast<const uint4*>(g_vwh + vw + 256);
            uint4 p0, p1;
            p0.x = prmtb(a.x, c.x, 0x5410); p0.y = prmtb(a.x, c.x, 0x7632);
            p0.z = prmtb(a.y, c.y, 0x5410); p0.w = prmtb(a.y, c.y, 0x7632);
            p1.x = prmtb(a.z, c.z, 0x5410); p1.y = prmtb(a.z, c.z, 0x7632);
            p1.z = prmtb(a.w, c.w, 0x5410); p1.w = prmtb(a.w, c.w, 0x7632);
            *reinterpret_cast<uint4*>(&Vph[pr][q * 8])     = p0;
            *reinterpret_cast<uint4*>(&Vph[pr][q * 8 + 4]) = p1;
            a = *reinterpret_cast<const uint4*>(g_vwl + vw);
            c = *reinterpret_cast<const uint4*>(g_vwl + vw + 256);
            p0.x = prmtb(a.x, c.x, 0x5410); p0.y = prmtb(a.x, c.x, 0x7632);
            p0.z = prmtb(a.y, c.y, 0x5410); p0.w = prmtb(a.y, c.y, 0x7632);
            p1.x = prmtb(a.z, c.z, 0x5410); p1.y = prmtb(a.z, c.z, 0x7632);
            p1.z = prmtb(a.w, c.w, 0x5410); p1.w = prmtb(a.w, c.w, 0x7632);
            *reinterpret_cast<uint4*>(&Vpl[pr][q * 8])     = p0;
            *reinterpret_cast<uint4*>(&Vpl[pr][q * 8 + 4]) = p1;
        }
        __syncthreads();

        // S = Q K^T (unscaled), term-ordered passes
        float sc[16][4];
#pragma unroll
        for (int nt = 0; nt < 16; nt++) {
            sc[nt][0] = sc[nt][1] = sc[nt][2] = sc[nt][3] = 0.f;
        }
#pragma unroll
        for (int kc = 0; kc < 4; kc++) {
#pragma unroll
            for (int half = 0; half < 2; half++) {
                unsigned kh0[8], kh1[8], kl0[8], kl1[8];
#pragma unroll
                for (int j = 0; j < 8; j++) {
                    int nt = half * 8 + j;
                    kh0[j] = Kph[nt * 8 + g][kc * 8 + tg];
                    kh1[j] = Kph[nt * 8 + g][kc * 8 + tg + 4];
                    kl0[j] = Kpl[nt * 8 + g][kc * 8 + tg];
                    kl1[j] = Kpl[nt * 8 + g][kc * 8 + tg + 4];
                }
#pragma unroll
                for (int j = 0; j < 8; j++)
                    mma16(sc[half * 8 + j], qh[kc], kh0[j], kh1[j]);
#pragma unroll
                for (int j = 0; j < 8; j++)
                    mma16(sc[half * 8 + j], ql[kc], kh0[j], kh1[j]);
#pragma unroll
                for (int j = 0; j < 8; j++)
                    mma16(sc[half * 8 + j], qh[kc], kl0[j], kl1[j]);
            }
        }

        // online softmax; scale 0.125 applied here
        float mx0 = -1e30f, mx1 = -1e30f;
#pragma unroll
        for (int nt = 0; nt < 16; nt++) {
            mx0 = fmaxf(mx0, fmaxf(sc[nt][0], sc[nt][1]));
            mx1 = fmaxf(mx1, fmaxf(sc[nt][2], sc[nt][3]));
        }
        mx0 = fmaxf(mx0, __shfl_xor_sync(0xffffffff, mx0, 1));
        mx0 = fmaxf(mx0, __shfl_xor_sync(0xffffffff, mx0, 2));
        mx1 = fmaxf(mx1, __shfl_xor_sync(0xffffffff, mx1, 1));
        mx1 = fmaxf(mx1, __shfl_xor_sync(0xffffffff, mx1, 2));
        float mn0 = fmaxf(mr0, mx0), mn1 = fmaxf(mr1, mx1);
        float al0 = __expf((mr0 - mn0) * 0.125f);
        float al1 = __expf((mr1 - mn1) * 0.125f);
        float ps0 = 0.f, ps1 = 0.f;
#pragma unroll
        for (int nt = 0; nt < 16; nt++) {
            sc[nt][0] = __expf((sc[nt][0] - mn0) * 0.125f);
            sc[nt][1] = __expf((sc[nt][1] - mn0) * 0.125f);
            sc[nt][2] = __expf((sc[nt][2] - mn1) * 0.125f);
            sc[nt][3] = __expf((sc[nt][3] - mn1) * 0.125f);
            ps0 += sc[nt][0] + sc[nt][1];
            ps1 += sc[nt][2] + sc[nt][3];
        }
        ps0 += __shfl_xor_sync(0xffffffff, ps0, 1);
        ps0 += __shfl_xor_sync(0xffffffff, ps0, 2);
        ps1 += __shfl_xor_sync(0xffffffff, ps1, 1);
        ps1 += __shfl_xor_sync(0xffffffff, ps1, 2);
        l0 = l0 * al0 + ps0;
        l1 = l1 * al1 + ps1;
        mr0 = mn0; mr1 = mn1;
#pragma unroll
        for (int dt = 0; dt < 8; dt++) {
            oa[dt][0] *= al0; oa[dt][1] *= al0;
            oa[dt][2] *= al1; oa[dt][3] *= al1;
        }

        // O += P V
#pragma unroll
        for (int nt2 = 0; nt2 < 8; nt2++) {
            const float* s0 = sc[2 * nt2];
            const float* s1 = sc[2 * nt2 + 1];
            unsigned pah[4], pal[4];
            split2(s0[0], s0[1], pah[0], pal[0]);
            split2(s0[2], s0[3], pah[1], pal[1]);
            split2(s1[0], s1[1], pah[2], pal[2]);
            split2(s1[2], s1[3], pah[3], pal[3]);
            unsigned vh0[8], vh1[8], vl0[8], vl1[8];
#pragma unroll
            for (int dt = 0; dt < 8; dt++) {
                vh0[dt] = Vph[nt2 * 8 + tg][dt * 8 + g];
                vh1[dt] = Vph[nt2 * 8 + tg + 4][dt * 8 + g];
                vl0[dt] = Vpl[nt2 * 8 + tg][dt * 8 + g];
                vl1[dt] = Vpl[nt2 * 8 + tg + 4][dt * 8 + g];
            }
#pragma unroll
            for (int dt = 0; dt < 8; dt++)
                mma16(oa[dt], pah, vh0[dt], vh1[dt]);
#pragma unroll
            for (int dt = 0; dt < 8; dt++)
                mma16(oa[dt], pal, vh0[dt], vh1[dt]);
#pragma unroll
            for (int dt = 0; dt < 8; dt++)
                mma16(oa[dt], pah, vl0[dt], vl1[dt]);
        }
        __syncthreads();
    }

    const float inv0 = 1.f / l0, inv1 = 1.f / l1;

    // O -> smem (64 rows x 64 d), then pair-pack along channel and store
    float (*Os)[68] = reinterpret_cast<float(*)[68]>(smem_u);
#pragma unroll
    for (int dt = 0; dt < 8; dt++) {
        Os[r0l][dt * 8 + 2 * tg]     = oa[dt][0] * inv0;
        Os[r0l][dt * 8 + 2 * tg + 1] = oa[dt][1] * inv0;
        Os[r1l][dt * 8 + 2 * tg]     = oa[dt][2] * inv1;
        Os[r1l][dt * 8 + 2 * tg + 1] = oa[dt][3] * inv1;
    }
    __syncthreads();
#pragma unroll
    for (int it = 0; it < 16; it++) {
        int f = tid + it * 128;
        int jp = f >> 6, nl = f & 63;
        unsigned hw, lw;
        split2(Os[nl][2 * jp], Os[nl][2 * jp + 1], hw, lw);
        size_t o = (size_t)b * PAIRS_B + (size_t)((hoff >> 1) + jp) * 1024 + n0 + nl;
        g_aph[o] = hw;
        g_apl[o] = lw;
    }
}

// --------------------- InstanceNorm (channel pair) ------------------------
// one CTA per channel pair; writes pair-packed bf16 hi/lo
__global__ __launch_bounds__(256)
void inorm2_kernel()
{
    __shared__ float ss[8], sq[8], stats[4];
    __shared__ float sbuf[2][1024];
    const float* p = g_o1 + (size_t)blockIdx.x * 2048;
    const int tid = threadIdx.x, lane = tid & 31, warp = tid >> 5;
    const int ch = tid >> 7, i2 = tid & 127;
    const float* row = p + ch * 1024;
    float4 a = reinterpret_cast<const float4*>(row)[i2 * 2];
    float4 c = reinterpret_cast<const float4*>(row)[i2 * 2 + 1];
    float s = a.x + a.y + a.z + a.w + c.x + c.y + c.z + c.w;
    float q = a.x * a.x + a.y * a.y + a.z * a.z + a.w * a.w
            + c.x * c.x + c.y * c.y + c.z * c.z + c.w * c.w;
#pragma unroll
    for (int off = 16; off > 0; off >>= 1) {
        s += __shfl_xor_sync(0xffffffff, s, off);
        q += __shfl_xor_sync(0xffffffff, q, off);
    }
    if (lane == 0) { ss[warp] = s; sq[warp] = q; }
    __syncthreads();
    if (tid == 0 || tid == 128) {
        int base = ch * 4;
        float S = ss[base] + ss[base + 1] + ss[base + 2] + ss[base + 3];
        float Qs = sq[base] + sq[base + 1] + sq[base + 2] + sq[base + 3];
        float mean = S * (1.f / SP);
        float var = Qs * (1.f / SP) - mean * mean;
        stats[ch * 2] = mean;
        stats[ch * 2 + 1] = rsqrtf(var + 1e-5f);
    }
    __syncthreads();
    float mean = stats[ch * 2], inv = stats[ch * 2 + 1];
    float* dst = &sbuf[ch][i2 * 8];
    dst[0] = (a.x - mean) * inv; dst[1] = (a.y - mean) * inv;
    dst[2] = (a.z - mean) * inv; dst[3] = (a.w - mean) * inv;
    dst[4] = (c.x - mean) * inv; dst[5] = (c.y - mean) * inv;
    dst[6] = (c.z - mean) * inv; dst[7] = (c.w - mean) * inv;
    __syncthreads();
#pragma unroll
    for (int it = 0; it < 4; it++) {
        int sidx = tid + it * 256;
        unsigned hw, lw;
        split2(sbuf[0][sidx], sbuf[1][sidx], hw, lw);
        g_oph[(size_t)blockIdx.x * 1024 + sidx] = hw;
        g_opl[(size_t)blockIdx.x * 1024 + sidx] = lw;
    }
}

// ---------------------------------------------------------------------------
extern "C" void kernel_launch(void* const* d_in, const int* in_sizes, int n_in,
                              void* d_out, int out_size)
{
    const float* x  = (const float*)d_in[0];
    const float* Wq = (const float*)d_in[1];
    const float* bq = (const float*)d_in[2];
    const float* Wk = (const float*)d_in[3];
    const float* bk = (const float*)d_in[4];
    const float* Wv = (const float*)d_in[5];
    const float* bv = (const float*)d_in[6];
    const float* Wo = (const float*)d_in[7];
    const float* bo = (const float*)d_in[8];

    unsigned *wwh, *wwl, *aph, *apl, *oph, *opl;
    float *o1;
    cudaGetSymbolAddress((void**)&wwh, g_wwh);
    cudaGetSymbolAddress((void**)&wwl, g_wwl);
    cudaGetSymbolAddress((void**)&aph, g_aph);
    cudaGetSymbolAddress((void**)&apl, g_apl);
    cudaGetSymbolAddress((void**)&oph, g_oph);
    cudaGetSymbolAddress((void**)&opl, g_opl);
    cudaGetSymbolAddress((void**)&o1,  g_o1);

    cudaFuncSetAttribute(attn_kernel, cudaFuncAttributeMaxDynamicSharedMemorySize, ATTN_SMEM);

    wsplit_kernel<<<2048, 256>>>(Wq, Wk, Wv, Wo);
    xsplit_kernel<<<4096, 256>>>(x);

    qkv_kernel<<<dim3(8, 12, BATCH), 256, GEMM_SMEM>>>(bq, bk, bv);

    attn_kernel<<<dim3(16, 8, BATCH), 128, ATTN_SMEM>>>();

    const unsigned* woh = wwh + 3 * 131072;
    const unsigned* wol = wwl + 3 * 131072;
    gemm_f_kernel<<<dim3(8, 4, BATCH), 256, GEMM_SMEM>>>(woh, wol, bo, aph, apl, o1);
    inorm2_kernel<<<BATCH * 256, 256>>>();
    gemm_f_kernel<<<dim3(8, 4, BATCH), 256, GEMM_SMEM>>>(woh, wol, bo, oph, opl, (float*)d_out);
}

// round 10
// speedup vs baseline: 1.4327x; 1.4327x over previous
#include <cuda_runtime.h>
#include <cuda_fp16.h>
#include <cstdint>

// ---------------------------------------------------------------------------
// B=16, C=512, S=1024, HEAD=8, D_K=64
// heads view: token n -> channel n>>1, feature j=h*64+d -> spatial ((n&1)<<9)+j
// FP16 2-term compensated: A*B ~= (Ah+Al)*Bh  (error = B fp16-rounding ~2^-12)
// A-side (W, Q, P) split hi/lo fp16; B-side (X, K, V, att, o1) fp16 hi only.
// mma.sync m16n8k16 f16 (tcgen05 unavailable: harness targets sm_103, no 'a').
// ---------------------------------------------------------------------------
#define BATCH   16
#define CH      512
#define SP      1024
#define PER_B   (CH*SP)
#define WORDS_B (PER_B/2)

// scratch
__device__ unsigned g_wwh[4*512*256], g_wwl[4*512*256];  // W fp16 pairs along k (hi/lo)
__device__ unsigned g_xph[BATCH*WORDS_B];                // X pairs along k, hi
__device__ unsigned g_qwh[BATCH*WORDS_B], g_qwl[BATCH*WORDS_B];
__device__ unsigned g_kwh[BATCH*WORDS_B];
__device__ unsigned g_vwh[BATCH*WORDS_B];
__device__ unsigned g_aph[BATCH*WORDS_B];                // attn out, pairs along ch, hi
__device__ float    g_o1[BATCH*PER_B];
__device__ unsigned g_oph[BATCH*WORDS_B];                // normed o1, pairs along ch, hi

__device__ __forceinline__ unsigned packh(float a, float b) {   // low=a, high=b
    unsigned r;
    asm("cvt.rn.f16x2.f32 %0, %1, %2;" : "=r"(r) : "f"(b), "f"(a));
    return r;
}
__device__ __forceinline__ void split2h(float a, float b, unsigned& hi, unsigned& lo) {
    hi = packh(a, b);
    __half2 h = *reinterpret_cast<__half2*>(&hi);
    lo = packh(a - __half2float(__low2half(h)), b - __half2float(__high2half(h)));
}
__device__ __forceinline__ unsigned prmtb(unsigned a, unsigned b, unsigned sel) {
    unsigned d;
    asm("prmt.b32 %0,%1,%2,%3;" : "=r"(d) : "r"(a), "r"(b), "r"(sel));
    return d;
}
__device__ __forceinline__ void mma16(float* c, const unsigned* a, unsigned b0, unsigned b1) {
    asm volatile(
        "mma.sync.aligned.m16n8k16.row.col.f32.f16.f16.f32 "
        "{%0,%1,%2,%3},{%4,%5,%6,%7},{%8,%9},{%0,%1,%2,%3};"
        : "+f"(c[0]), "+f"(c[1]), "+f"(c[2]), "+f"(c[3])
        : "r"(a[0]), "r"(a[1]), "r"(a[2]), "r"(a[3]), "r"(b0), "r"(b1));
}

// ------------------------------ prepasses ---------------------------------
__global__ __launch_bounds__(256)
void wsplit_kernel(const float* __restrict__ Wq, const float* __restrict__ Wk,
                   const float* __restrict__ Wv, const float* __restrict__ Wo)
{
    unsigned w = blockIdx.x * 256 + threadIdx.x;     // 524288 words
    unsigned m = w >> 17, rem = w & 131071;
    const float* src = m == 0 ? Wq : (m == 1 ? Wk : (m == 2 ? Wv : Wo));
    float2 v = reinterpret_cast<const float2*>(src)[rem];
    unsigned h, l;
    split2h(v.x, v.y, h, l);
    g_wwh[w] = h; g_wwl[w] = l;
}

__global__ __launch_bounds__(256)
void xsplit_kernel(const float* __restrict__ X)
{
    unsigned f = blockIdx.x * 256 + threadIdx.x;     // 1048576 uint4 items
    unsigned b = f >> 16;
    unsigned kp = (f >> 8) & 255;
    unsigned n4 = (f & 255) << 2;
    const float* p = X + (size_t)b * PER_B + (size_t)(2 * kp) * SP + n4;
    float4 a = *reinterpret_cast<const float4*>(p);
    float4 c = *reinterpret_cast<const float4*>(p + SP);
    uint4 h;
    h.x = packh(a.x, c.x); h.y = packh(a.y, c.y);
    h.z = packh(a.z, c.z); h.w = packh(a.w, c.w);
    *reinterpret_cast<uint4*>(g_xph + (size_t)b * WORDS_B + (size_t)kp * 1024 + n4) = h;
}

// ------------------------------ GEMM core ---------------------------------
// acc = W[128xK] @ B[Kx128]; A hi/lo, B hi only.
// smem: Ahp/Alp[128][20], Bph[16][132] = 28928 B
#define GEMM_SMEM ((2*128*20 + 16*132) * 4)

__device__ __forceinline__ void gemm_acc(
    const unsigned* __restrict__ awh, const unsigned* __restrict__ awl,
    const unsigned* __restrict__ bph, int m0, int n0, unsigned* gsm, float acc[2][8][4])
{
    unsigned (*Ahp)[20]  = reinterpret_cast<unsigned(*)[20]>(gsm);
    unsigned (*Alp)[20]  = reinterpret_cast<unsigned(*)[20]>(gsm + 128*20);
    unsigned (*Bph)[132] = reinterpret_cast<unsigned(*)[132]>(gsm + 2*128*20);

    const int tid = threadIdx.x, lane = tid & 31, warp = tid >> 5;
    const int wm = warp & 3, wn = warp >> 2;
    const int g = lane >> 2, tg = lane & 3;

#pragma unroll
    for (int mt = 0; mt < 2; mt++)
#pragma unroll
        for (int nt = 0; nt < 8; nt++)
#pragma unroll
            for (int i = 0; i < 4; i++) acc[mt][nt][i] = 0.f;

    for (int kp0 = 0; kp0 < 256; kp0 += 16) {
#pragma unroll
        for (int i = 0; i < 4; i++) {
            int f = tid + i * 256;
            int r = f >> 3, u = (f & 7) << 1;
            size_t src = (size_t)(m0 + r) * 256 + kp0 + u;
            *reinterpret_cast<uint2*>(&Ahp[r][u]) = *reinterpret_cast<const uint2*>(awh + src);
            *reinterpret_cast<uint2*>(&Alp[r][u]) = *reinterpret_cast<const uint2*>(awl + src);
        }
#pragma unroll
        for (int i = 0; i < 2; i++) {
            int f = tid + i * 256;
            int kp = f >> 5, n4 = (f & 31) << 2;
            size_t src = (size_t)(kp0 + kp) * 1024 + n0 + n4;
            *reinterpret_cast<uint4*>(&Bph[kp][n4]) = *reinterpret_cast<const uint4*>(bph + src);
        }
        __syncthreads();

#pragma unroll
        for (int kc = 0; kc < 2; kc++) {
            const int base = kc * 8;
            unsigned ah[2][4], al[2][4];
#pragma unroll
            for (int mt = 0; mt < 2; mt++) {
                int rm = wm * 32 + mt * 16;
                ah[mt][0] = Ahp[rm + g][base + tg];
                ah[mt][1] = Ahp[rm + g + 8][base + tg];
                ah[mt][2] = Ahp[rm + g][base + tg + 4];
                ah[mt][3] = Ahp[rm + g + 8][base + tg + 4];
                al[mt][0] = Alp[rm + g][base + tg];
                al[mt][1] = Alp[rm + g + 8][base + tg];
                al[mt][2] = Alp[rm + g][base + tg + 4];
                al[mt][3] = Alp[rm + g + 8][base + tg + 4];
            }
#pragma unroll
            for (int ntc = 0; ntc < 2; ntc++) {
                unsigned bh0[4], bh1[4];
#pragma unroll
                for (int j = 0; j < 4; j++) {
                    int cn = wn * 64 + (ntc * 4 + j) * 8;
                    bh0[j] = Bph[base + tg][cn + g];
                    bh1[j] = Bph[base + tg + 4][cn + g];
                }
#pragma unroll
                for (int j = 0; j < 4; j++) {
                    mma16(acc[0][ntc * 4 + j], ah[0], bh0[j], bh1[j]);
                    mma16(acc[1][ntc * 4 + j], ah[1], bh0[j], bh1[j]);
                }
#pragma unroll
                for (int j = 0; j < 4; j++) {
                    mma16(acc[0][ntc * 4 + j], al[0], bh0[j], bh1[j]);
                    mma16(acc[1][ntc * 4 + j], al[1], bh0[j], bh1[j]);
                }
            }
        }
        __syncthreads();
    }
}

// fused QKV: grid (8, 12, 16); y>>2 selects {Q,K,V}
__global__ __launch_bounds__(256, 2)
void qkv_kernel(const float* __restrict__ bq, const float* __restrict__ bk,
                const float* __restrict__ bv)
{
    extern __shared__ unsigned gsm[];
    const int sel = blockIdx.y >> 2;
    const int m0 = (blockIdx.y & 3) * 128;
    const int n0 = blockIdx.x * 128;
    const int b  = blockIdx.z;
    const unsigned* awh = g_wwh + sel * 131072;
    const unsigned* awl = g_wwl + sel * 131072;
    const unsigned* bph = g_xph + (size_t)b * WORDS_B;
    const float* bias = sel == 0 ? bq : (sel == 1 ? bk : bv);
    unsigned* oh = (sel == 0 ? g_qwh : (sel == 1 ? g_kwh : g_vwh)) + (size_t)b * WORDS_B;
    unsigned* ol = g_qwl + (size_t)b * WORDS_B;

    float acc[2][8][4];
    gemm_acc(awh, awl, bph, m0, n0, gsm, acc);

    const int tid = threadIdx.x, lane = tid & 31, warp = tid >> 5;
    const int wm = warp & 3, wn = warp >> 2;
    const int g = lane >> 2, tg = lane & 3;
#pragma unroll
    for (int mt = 0; mt < 2; mt++) {
        int r0 = m0 + wm * 32 + mt * 16 + g;
        float bi0 = bias[r0], bi1 = bias[r0 + 8];
#pragma unroll
        for (int nt = 0; nt < 8; nt++) {
            int cn = n0 + wn * 64 + nt * 8 + 2 * tg;
            unsigned h, l;
            split2h(acc[mt][nt][0] + bi0, acc[mt][nt][1] + bi0, h, l);
            oh[(size_t)r0 * 512 + (cn >> 1)] = h;
            if (sel == 0) ol[(size_t)r0 * 512 + (cn >> 1)] = l;
            split2h(acc[mt][nt][2] + bi1, acc[mt][nt][3] + bi1, h, l);
            oh[(size_t)(r0 + 8) * 512 + (cn >> 1)] = h;
            if (sel == 0) ol[(size_t)(r0 + 8) * 512 + (cn >> 1)] = l;
        }
    }
}

// O-conv GEMM: A = Wo hi/lo, B = pair-packed hi; float out
__global__ __launch_bounds__(256, 2)
void gemm_f_kernel(const float* __restrict__ bias,
                   const unsigned* __restrict__ bph_all, float* __restrict__ Y)
{
    extern __shared__ unsigned gsm[];
    const int m0 = blockIdx.y * 128, n0 = blockIdx.x * 128, b = blockIdx.z;
    const unsigned* bph = bph_all + (size_t)b * WORDS_B;
    float* Yb = Y + (size_t)b * PER_B;

    float acc[2][8][4];
    gemm_acc(g_wwh + 3 * 131072, g_wwl + 3 * 131072, bph, m0, n0, gsm, acc);

    const int tid = threadIdx.x, lane = tid & 31, warp = tid >> 5;
    const int wm = warp & 3, wn = warp >> 2;
    const int g = lane >> 2, tg = lane & 3;
#pragma unroll
    for (int mt = 0; mt < 2; mt++) {
        int r0 = m0 + wm * 32 + mt * 16 + g;
        float bi0 = bias[r0], bi1 = bias[r0 + 8];
#pragma unroll
        for (int nt = 0; nt < 8; nt++) {
            int cn = n0 + wn * 64 + nt * 8 + 2 * tg;
            Yb[(size_t)r0 * SP + cn]           = acc[mt][nt][0] + bi0;
            Yb[(size_t)r0 * SP + cn + 1]       = acc[mt][nt][1] + bi0;
            Yb[(size_t)(r0 + 8) * SP + cn]     = acc[mt][nt][2] + bi1;
            Yb[(size_t)(r0 + 8) * SP + cn + 1] = acc[mt][nt][3] + bi1;
        }
    }
}

// ------------------------------ attention ---------------------------------
// grid (8 qblocks of 128 rows, 8 heads, 16 b), 256 thr, 2 CTAs/SM target.
// 64-key tiles (16 iters). smem loop use: Kh[64][36]+Vh[32][72]=18432B;
// epilogue Os[128][68] floats = 34816B -> ATTN_SMEM = 34816
#define ATTN_SMEM (128*68*4)

__device__ __forceinline__ size_t tok_off(int n, int hoff) {
    return (size_t)(n >> 1) * SP + ((n & 1) << 9) + hoff;
}

__global__ __launch_bounds__(256, 2)
void attn_kernel()
{
    extern __shared__ unsigned smem_u[];
    unsigned (*Kh)[36] = reinterpret_cast<unsigned(*)[36]>(smem_u);
    unsigned (*Vh)[72] = reinterpret_cast<unsigned(*)[72]>(smem_u + 64*36);

    const int tid = threadIdx.x, lane = tid & 31, warp = tid >> 5;
    const int g = lane >> 2, tg = lane & 3;

    const int b = blockIdx.z, h = blockIdx.y;
    const int n0 = blockIdx.x * 128;
    const size_t bbw = (size_t)b * WORDS_B;
    const int hoff = h * 64;

    // Q fragments (hi/lo); 1/8 scale folded into softmax
    const int r0l = warp * 16 + g, r1l = r0l + 8;
    const size_t w0 = bbw + (tok_off(n0 + r0l, hoff) >> 1);
    const size_t w1 = bbw + (tok_off(n0 + r1l, hoff) >> 1);
    unsigned qh[4][4], ql[4][4];
#pragma unroll
    for (int kc = 0; kc < 4; kc++) {
        qh[kc][0] = g_qwh[w0 + kc * 8 + tg];
        qh[kc][1] = g_qwh[w1 + kc * 8 + tg];
        qh[kc][2] = g_qwh[w0 + kc * 8 + tg + 4];
        qh[kc][3] = g_qwh[w1 + kc * 8 + tg + 4];
        ql[kc][0] = g_qwl[w0 + kc * 8 + tg];
        ql[kc][1] = g_qwl[w1 + kc * 8 + tg];
        ql[kc][2] = g_qwl[w0 + kc * 8 + tg + 4];
        ql[kc][3] = g_qwl[w1 + kc * 8 + tg + 4];
    }

    float mr0 = -1e30f, mr1 = -1e30f, l0 = 0.f, l1 = 0.f;
    float oa[8][4];
#pragma unroll
    for (int dt = 0; dt < 8; dt++)
#pragma unroll
        for (int i = 0; i < 4; i++) oa[dt][i] = 0.f;

    for (int t = 0; t < 16; t++) {
        // K tile: 64 keys x 32 words (pairs along d), hi only
#pragma unroll
        for (int i = 0; i < 2; i++) {
            int f = tid + i * 256;
            int r = f >> 3, q4 = (f & 7) << 2;
            size_t kw = bbw + (tok_off(t * 64 + r, hoff) >> 1) + q4;
            *reinterpret_cast<uint4*>(&Kh[r][q4]) = *reinterpret_cast<const uint4*>(g_kwh + kw);
        }
        // V tile: 32 key-pair rows x 64 words (pairs along key), hi only
        {
            int pr = tid >> 3, q = tid & 7;
            size_t vw = bbw + (size_t)(t * 32 + pr) * 512 + (hoff >> 1) + q * 4;
            uint4 a = *reinterpret_cast<const uint4*>(g_vwh + vw);
            uint4 c = *reinterpret_cast<const uint4*>(g_vwh + vw + 256);
            uint4 p0, p1;
            p0.x = prmtb(a.x, c.x, 0x5410); p0.y = prmtb(a.x, c.x, 0x7632);
            p0.z = prmtb(a.y, c.y, 0x5410); p0.w = prmtb(a.y, c.y, 0x7632);
            p1.x = prmtb(a.z, c.z, 0x5410); p1.y = prmtb(a.z, c.z, 0x7632);
            p1.z = prmtb(a.w, c.w, 0x5410); p1.w = prmtb(a.w, c.w, 0x7632);
            *reinterpret_cast<uint4*>(&Vh[pr][q * 8])     = p0;
            *reinterpret_cast<uint4*>(&Vh[pr][q * 8 + 4]) = p1;
        }
        __syncthreads();

        // S = Q K^T : 8 n-tiles, 2-term passes
        float sc[8][4];
#pragma unroll
        for (int nt = 0; nt < 8; nt++) {
            sc[nt][0] = sc[nt][1] = sc[nt][2] = sc[nt][3] = 0.f;
        }
#pragma unroll
        for (int kc = 0; kc < 4; kc++) {
            unsigned kh0[8], kh1[8];
#pragma unroll
            for (int j = 0; j < 8; j++) {
                kh0[j] = Kh[j * 8 + g][kc * 8 + tg];
                kh1[j] = Kh[j * 8 + g][kc * 8 + tg + 4];
            }
#pragma unroll
            for (int j = 0; j < 8; j++)
                mma16(sc[j], qh[kc], kh0[j], kh1[j]);
#pragma unroll
            for (int j = 0; j < 8; j++)
                mma16(sc[j], ql[kc], kh0[j], kh1[j]);
        }

        // online softmax (scale 0.125 here)
        float mx0 = -1e30f, mx1 = -1e30f;
#pragma unroll
        for (int nt = 0; nt < 8; nt++) {
            mx0 = fmaxf(mx0, fmaxf(sc[nt][0], sc[nt][1]));
            mx1 = fmaxf(mx1, fmaxf(sc[nt][2], sc[nt][3]));
        }
        mx0 = fmaxf(mx0, __shfl_xor_sync(0xffffffff, mx0, 1));
        mx0 = fmaxf(mx0, __shfl_xor_sync(0xffffffff, mx0, 2));
        mx1 = fmaxf(mx1, __shfl_xor_sync(0xffffffff, mx1, 1));
        mx1 = fmaxf(mx1, __shfl_xor_sync(0xffffffff, mx1, 2));
        float mn0 = fmaxf(mr0, mx0), mn1 = fmaxf(mr1, mx1);
        float al0 = __expf((mr0 - mn0) * 0.125f);
        float al1 = __expf((mr1 - mn1) * 0.125f);
        float ps0 = 0.f, ps1 = 0.f;
#pragma unroll
        for (int nt = 0; nt < 8; nt++) {
            sc[nt][0] = __expf((sc[nt][0] - mn0) * 0.125f);
            sc[nt][1] = __expf((sc[nt][1] - mn0) * 0.125f);
            sc[nt][2] = __expf((sc[nt][2] - mn1) * 0.125f);
            sc[nt][3] = __expf((sc[nt][3] - mn1) * 0.125f);
            ps0 += sc[nt][0] + sc[nt][1];
            ps1 += sc[nt][2] + sc[nt][3];
        }
        ps0 += __shfl_xor_sync(0xffffffff, ps0, 1);
        ps0 += __shfl_xor_sync(0xffffffff, ps0, 2);
        ps1 += __shfl_xor_sync(0xffffffff, ps1, 1);
        ps1 += __shfl_xor_sync(0xffffffff, ps1, 2);
        l0 = l0 * al0 + ps0;
        l1 = l1 * al1 + ps1;
        mr0 = mn0; mr1 = mn1;
#pragma unroll
        for (int dt = 0; dt < 8; dt++) {
            oa[dt][0] *= al0; oa[dt][1] *= al0;
            oa[dt][2] *= al1; oa[dt][3] *= al1;
        }

        // O += P V : 4 key-chunks, P split hi/lo, V hi only
#pragma unroll
        for (int nt2 = 0; nt2 < 4; nt2++) {
            const float* s0 = sc[2 * nt2];
            const float* s1 = sc[2 * nt2 + 1];
            unsigned pah[4], pal[4];
            split2h(s0[0], s0[1], pah[0], pal[0]);
            split2h(s0[2], s0[3], pah[1], pal[1]);
            split2h(s1[0], s1[1], pah[2], pal[2]);
            split2h(s1[2], s1[3], pah[3], pal[3]);
            unsigned vh0[8], vh1[8];
#pragma unroll
            for (int dt = 0; dt < 8; dt++) {
                vh0[dt] = Vh[nt2 * 8 + tg][dt * 8 + g];
                vh1[dt] = Vh[nt2 * 8 + tg + 4][dt * 8 + g];
            }
#pragma unroll
            for (int dt = 0; dt < 8; dt++)
                mma16(oa[dt], pah, vh0[dt], vh1[dt]);
#pragma unroll
            for (int dt = 0; dt < 8; dt++)
                mma16(oa[dt], pal, vh0[dt], vh1[dt]);
        }
        __syncthreads();
    }

    const float inv0 = 1.f / l0, inv1 = 1.f / l1;

    // O -> smem (128 rows x 64 d), then pair-pack along channel (hi) and store
    float (*Os)[68] = reinterpret_cast<float(*)[68]>(smem_u);
#pragma unroll
    for (int dt = 0; dt < 8; dt++) {
        Os[r0l][dt * 8 + 2 * tg]     = oa[dt][0] * inv0;
        Os[r0l][dt * 8 + 2 * tg + 1] = oa[dt][1] * inv0;
        Os[r1l][dt * 8 + 2 * tg]     = oa[dt][2] * inv1;
        Os[r1l][dt * 8 + 2 * tg + 1] = oa[dt][3] * inv1;
    }
    __syncthreads();
#pragma unroll
    for (int it = 0; it < 16; it++) {
        int f = tid + it * 256;
        int jp = f >> 7, nl = f & 127;
        g_aph[bbw + (size_t)((hoff >> 1) + jp) * 1024 + n0 + nl]
            = packh(Os[nl][2 * jp], Os[nl][2 * jp + 1]);
    }
}

// --------------------- InstanceNorm (channel pair) ------------------------
__global__ __launch_bounds__(256)
void inorm2_kernel()
{
    __shared__ float ss[8], sq[8], stats[4];
    __shared__ float sbuf[2][1024];
    const float* p = g_o1 + (size_t)blockIdx.x * 2048;
    const int tid = threadIdx.x, lane = tid & 31, warp = tid >> 5;
    const int ch = tid >> 7, i2 = tid & 127;
    const float* row = p + ch * 1024;
    float4 a = reinterpret_cast<const float4*>(row)[i2 * 2];
    float4 c = reinterpret_cast<const float4*>(row)[i2 * 2 + 1];
    float s = a.x + a.y + a.z + a.w + c.x + c.y + c.z + c.w;
    float q = a.x * a.x + a.y * a.y + a.z * a.z + a.w * a.w
            + c.x * c.x + c.y * c.y + c.z * c.z + c.w * c.w;
#pragma unroll
    for (int off = 16; off > 0; off >>= 1) {
        s += __shfl_xor_sync(0xffffffff, s, off);
        q += __shfl_xor_sync(0xffffffff, q, off);
    }
    if (lane == 0) { ss[warp] = s; sq[warp] = q; }
    __syncthreads();
    if (tid == 0 || tid == 128) {
        int base = ch * 4;
        float S = ss[base] + ss[base + 1] + ss[base + 2] + ss[base + 3];
        float Qs = sq[base] + sq[base + 1] + sq[base + 2] + sq[base + 3];
        float mean = S * (1.f / SP);
        float var = Qs * (1.f / SP) - mean * mean;
        stats[ch * 2] = mean;
        stats[ch * 2 + 1] = rsqrtf(var + 1e-5f);
    }
    __syncthreads();
    float mean = stats[ch * 2], inv = stats[ch * 2 + 1];
    float* dst = &sbuf[ch][i2 * 8];
    dst[0] = (a.x - mean) * inv; dst[1] = (a.y - mean) * inv;
    dst[2] = (a.z - mean) * inv; dst[3] = (a.w - mean) * inv;
    dst[4] = (c.x - mean) * inv; dst[5] = (c.y - mean) * inv;
    dst[6] = (c.z - mean) * inv; dst[7] = (c.w - mean) * inv;
    __syncthreads();
#pragma unroll
    for (int it = 0; it < 4; it++) {
        int sidx = tid + it * 256;
        g_oph[(size_t)blockIdx.x * 1024 + sidx] = packh(sbuf[0][sidx], sbuf[1][sidx]);
    }
}

// ---------------------------------------------------------------------------
extern "C" void kernel_launch(void* const* d_in, const int* in_sizes, int n_in,
                              void* d_out, int out_size)
{
    const float* x  = (const float*)d_in[0];
    const float* Wq = (const float*)d_in[1];
    const float* bq = (const float*)d_in[2];
    const float* Wk = (const float*)d_in[3];
    const float* bk = (const float*)d_in[4];
    const float* Wv = (const float*)d_in[5];
    const float* bv = (const float*)d_in[6];
    const float* Wo = (const float*)d_in[7];
    const float* bo = (const float*)d_in[8];

    unsigned *aph, *oph;
    float *o1;
    cudaGetSymbolAddress((void**)&aph, g_aph);
    cudaGetSymbolAddress((void**)&oph, g_oph);
    cudaGetSymbolAddress((void**)&o1,  g_o1);

    wsplit_kernel<<<2048, 256>>>(Wq, Wk, Wv, Wo);
    xsplit_kernel<<<4096, 256>>>(x);

    qkv_kernel<<<dim3(8, 12, BATCH), 256, GEMM_SMEM>>>(bq, bk, bv);

    attn_kernel<<<dim3(8, 8, BATCH), 256, ATTN_SMEM>>>();

    gemm_f_kernel<<<dim3(8, 4, BATCH), 256, GEMM_SMEM>>>(bo, aph, o1);
    inorm2_kernel<<<BATCH * 256, 256>>>();
    gemm_f_kernel<<<dim3(8, 4, BATCH), 256, GEMM_SMEM>>>(bo, oph, (float*)d_out);
}

// round 12
// speedup vs baseline: 1.6097x; 1.1236x over previous
#include <cuda_runtime.h>
#include <cuda_fp16.h>
#include <cstdint>

// ---------------------------------------------------------------------------
// B=16, C=512, S=1024, HEAD=8, D_K=64
// heads view: token n -> channel n>>1, feature j=h*64+d -> spatial ((n&1)<<9)+j
// FP16 2-term compensated: A*B ~= (Ah+Al)*Bh  (error = B fp16-rounding ~2^-12)
// A-side (W, Q, P) split hi/lo fp16; B-side (X, K, V, att, o1) fp16 hi only.
// cp.async 2-stage pipelines everywhere; softmax without running max
// (scores provably << fp32 exp range; softmax is shift-invariant).
// ---------------------------------------------------------------------------
#define BATCH   16
#define CH      512
#define SP      1024
#define PER_B   (CH*SP)
#define WORDS_B (PER_B/2)

__device__ unsigned g_wwh[4*512*256], g_wwl[4*512*256];
__device__ unsigned g_xph[BATCH*WORDS_B];
__device__ unsigned g_qwh[BATCH*WORDS_B], g_qwl[BATCH*WORDS_B];
__device__ unsigned g_kwh[BATCH*WORDS_B];
__device__ unsigned g_vwh[BATCH*WORDS_B];
__device__ unsigned g_aph[BATCH*WORDS_B];
__device__ float    g_o1[BATCH*PER_B];
__device__ unsigned g_oph[BATCH*WORDS_B];

__device__ __forceinline__ unsigned packh(float a, float b) {
    unsigned r;
    asm("cvt.rn.f16x2.f32 %0, %1, %2;" : "=r"(r) : "f"(b), "f"(a));
    return r;
}
__device__ __forceinline__ void split2h(float a, float b, unsigned& hi, unsigned& lo) {
    hi = packh(a, b);
    __half2 h = *reinterpret_cast<__half2*>(&hi);
    lo = packh(a - __half2float(__low2half(h)), b - __half2float(__high2half(h)));
}
__device__ __forceinline__ unsigned prmtb(unsigned a, unsigned b, unsigned sel) {
    unsigned d;
    asm("prmt.b32 %0,%1,%2,%3;" : "=r"(d) : "r"(a), "r"(b), "r"(sel));
    return d;
}
__device__ __forceinline__ void mma16(float* c, const unsigned* a, unsigned b0, unsigned b1) {
    asm volatile(
        "mma.sync.aligned.m16n8k16.row.col.f32.f16.f16.f32 "
        "{%0,%1,%2,%3},{%4,%5,%6,%7},{%8,%9},{%0,%1,%2,%3};"
        : "+f"(c[0]), "+f"(c[1]), "+f"(c[2]), "+f"(c[3])
        : "r"(a[0]), "r"(a[1]), "r"(a[2]), "r"(a[3]), "r"(b0), "r"(b1));
}
__device__ __forceinline__ void cpa16(uint32_t d, const void* s) {
    asm volatile("cp.async.cg.shared.global [%0], [%1], 16;" :: "r"(d), "l"(s));
}
#define CP_COMMIT() asm volatile("cp.async.commit_group;" ::: "memory")
#define CP_WAIT1()  asm volatile("cp.async.wait_group 1;" ::: "memory")
#define CP_WAIT0()  asm volatile("cp.async.wait_group 0;" ::: "memory")

// ------------------------------ prepasses ---------------------------------
__global__ __launch_bounds__(256)
void wsplit_kernel(const float* __restrict__ Wq, const float* __restrict__ Wk,
                   const float* __restrict__ Wv, const float* __restrict__ Wo)
{
    unsigned w = blockIdx.x * 256 + threadIdx.x;
    unsigned m = w >> 17, rem = w & 131071;
    const float* src = m == 0 ? Wq : (m == 1 ? Wk : (m == 2 ? Wv : Wo));
    float2 v = reinterpret_cast<const float2*>(src)[rem];
    unsigned h, l;
    split2h(v.x, v.y, h, l);
    g_wwh[w] = h; g_wwl[w] = l;
}

__global__ __launch_bounds__(256)
void xsplit_kernel(const float* __restrict__ X)
{
    unsigned f = blockIdx.x * 256 + threadIdx.x;
    unsigned b = f >> 16;
    unsigned kp = (f >> 8) & 255;
    unsigned n4 = (f & 255) << 2;
    const float* p = X + (size_t)b * PER_B + (size_t)(2 * kp) * SP + n4;
    float4 a = *reinterpret_cast<const float4*>(p);
    float4 c = *reinterpret_cast<const float4*>(p + SP);
    uint4 h;
    h.x = packh(a.x, c.x); h.y = packh(a.y, c.y);
    h.z = packh(a.z, c.z); h.w = packh(a.w, c.w);
    *reinterpret_cast<uint4*>(g_xph + (size_t)b * WORDS_B + (size_t)kp * 1024 + n4) = h;
}

// ------------------------------ GEMM core ---------------------------------
// double-buffered cp.async pipeline; 16 chunks of k=32 (16 pair-words).
// smem words: Abuf0[0..5120) (Ah 0..2560 stride20, Al 2560..), Abuf1[5120..10240),
//             Bbuf0[10240..12352) stride132, Bbuf1[12352..14464)
#define GEMM_SMEM (14464*4)

__device__ __forceinline__ void gemm_ld(uint32_t sb4, const unsigned* __restrict__ awh,
                                        const unsigned* __restrict__ awl,
                                        const unsigned* __restrict__ bph,
                                        int m0, int n0, int kp0, int bs, int tid)
{
    uint32_t abase = sb4 + bs * 5120 * 4;
#pragma unroll
    for (int i = 0; i < 2; i++) {
        int f = tid + i * 256;
        int r = f >> 2, seg = (f & 3) << 2;
        size_t src = (size_t)(m0 + r) * 256 + kp0 + seg;
        uint32_t d = abase + (r * 20 + seg) * 4;
        cpa16(d, awh + src);
        cpa16(d + 2560 * 4, awl + src);
    }
    uint32_t bbase = sb4 + (10240 + bs * 2112) * 4;
#pragma unroll
    for (int i = 0; i < 2; i++) {
        int f = tid + i * 256;
        int kp = f >> 5, seg = (f & 31) << 2;
        cpa16(bbase + (kp * 132 + seg) * 4,
              bph + (size_t)(kp0 + kp) * 1024 + n0 + seg);
    }
}

__device__ __forceinline__ void gemm_acc(
    const unsigned* __restrict__ awh, const unsigned* __restrict__ awl,
    const unsigned* __restrict__ bph, int m0, int n0, unsigned* gsm, float acc[2][8][4])
{
    const int tid = threadIdx.x, lane = tid & 31, warp = tid >> 5;
    const int wm = warp & 3, wn = warp >> 2;
    const int g = lane >> 2, tg = lane & 3;
    uint32_t sb4 = (uint32_t)__cvta_generic_to_shared(gsm);

#pragma unroll
    for (int mt = 0; mt < 2; mt++)
#pragma unroll
        for (int nt = 0; nt < 8; nt++)
#pragma unroll
            for (int i = 0; i < 4; i++) acc[mt][nt][i] = 0.f;

    gemm_ld(sb4, awh, awl, bph, m0, n0, 0, 0, tid);
    CP_COMMIT();

    for (int c = 0; c < 16; c++) {
        const int bs = c & 1;
        if (c < 15) {
            gemm_ld(sb4, awh, awl, bph, m0, n0, (c + 1) * 16, (c + 1) & 1, tid);
            CP_COMMIT();
            CP_WAIT1();
        } else {
            CP_WAIT0();
        }
        __syncthreads();

        unsigned (*Ahp)[20]  = reinterpret_cast<unsigned(*)[20]>(gsm + bs * 5120);
        unsigned (*Alp)[20]  = reinterpret_cast<unsigned(*)[20]>(gsm + bs * 5120 + 2560);
        unsigned (*Bph)[132] = reinterpret_cast<unsigned(*)[132]>(gsm + 10240 + bs * 2112);

#pragma unroll
        for (int kc = 0; kc < 2; kc++) {
            const int base = kc * 8;
            unsigned ah[2][4], al[2][4];
#pragma unroll
            for (int mt = 0; mt < 2; mt++) {
                int rm = wm * 32 + mt * 16;
                ah[mt][0] = Ahp[rm + g][base + tg];
                ah[mt][1] = Ahp[rm + g + 8][base + tg];
                ah[mt][2] = Ahp[rm + g][base + tg + 4];
                ah[mt][3] = Ahp[rm + g + 8][base + tg + 4];
                al[mt][0] = Alp[rm + g][base + tg];
                al[mt][1] = Alp[rm + g + 8][base + tg];
                al[mt][2] = Alp[rm + g][base + tg + 4];
                al[mt][3] = Alp[rm + g + 8][base + tg + 4];
            }
#pragma unroll
            for (int ntc = 0; ntc < 2; ntc++) {
                unsigned bh0[4], bh1[4];
#pragma unroll
                for (int j = 0; j < 4; j++) {
                    int cn = wn * 64 + (ntc * 4 + j) * 8;
                    bh0[j] = Bph[base + tg][cn + g];
                    bh1[j] = Bph[base + tg + 4][cn + g];
                }
#pragma unroll
                for (int j = 0; j < 4; j++) {
                    mma16(acc[0][ntc * 4 + j], ah[0], bh0[j], bh1[j]);
                    mma16(acc[1][ntc * 4 + j], ah[1], bh0[j], bh1[j]);
                }
#pragma unroll
                for (int j = 0; j < 4; j++) {
                    mma16(acc[0][ntc * 4 + j], al[0], bh0[j], bh1[j]);
                    mma16(acc[1][ntc * 4 + j], al[1], bh0[j], bh1[j]);
                }
            }
        }
        __syncthreads();
    }
}

// fused QKV: grid (8, 12, 16); y>>2 selects {Q,K,V}
__global__ __launch_bounds__(256, 2)
void qkv_kernel(const float* __restrict__ bq, const float* __restrict__ bk,
                const float* __restrict__ bv)
{
    extern __shared__ unsigned gsm[];
    const int sel = blockIdx.y >> 2;
    const int m0 = (blockIdx.y & 3) * 128;
    const int n0 = blockIdx.x * 128;
    const int b  = blockIdx.z;
    const unsigned* awh = g_wwh + sel * 131072;
    const unsigned* awl = g_wwl + sel * 131072;
    const unsigned* bph = g_xph + (size_t)b * WORDS_B;
    const float* bias = sel == 0 ? bq : (sel == 1 ? bk : bv);
    unsigned* oh = (sel == 0 ? g_qwh : (sel == 1 ? g_kwh : g_vwh)) + (size_t)b * WORDS_B;
    unsigned* ol = g_qwl + (size_t)b * WORDS_B;

    float acc[2][8][4];
    gemm_acc(awh, awl, bph, m0, n0, gsm, acc);

    const int tid = threadIdx.x, lane = tid & 31, warp = tid >> 5;
    const int wm = warp & 3, wn = warp >> 2;
    const int g = lane >> 2, tg = lane & 3;
#pragma unroll
    for (int mt = 0; mt < 2; mt++) {
        int r0 = m0 + wm * 32 + mt * 16 + g;
        float bi0 = bias[r0], bi1 = bias[r0 + 8];
#pragma unroll
        for (int nt = 0; nt < 8; nt++) {
            int cn = n0 + wn * 64 + nt * 8 + 2 * tg;
            unsigned h, l;
            split2h(acc[mt][nt][0] + bi0, acc[mt][nt][1] + bi0, h, l);
            oh[(size_t)r0 * 512 + (cn >> 1)] = h;
            if (sel == 0) ol[(size_t)r0 * 512 + (cn >> 1)] = l;
            split2h(acc[mt][nt][2] + bi1, acc[mt][nt][3] + bi1, h, l);
            oh[(size_t)(r0 + 8) * 512 + (cn >> 1)] = h;
            if (sel == 0) ol[(size_t)(r0 + 8) * 512 + (cn >> 1)] = l;
        }
    }
}

// O-conv GEMM: A = Wo hi/lo, B = pair-packed hi; float out
__global__ __launch_bounds__(256, 2)
void gemm_f_kernel(const float* __restrict__ bias,
                   const unsigned* __restrict__ bph_all, float* __restrict__ Y)
{
    extern __shared__ unsigned gsm[];
    const int m0 = blockIdx.y * 128, n0 = blockIdx.x * 128, b = blockIdx.z;
    const unsigned* bph = bph_all + (size_t)b * WORDS_B;
    float* Yb = Y + (size_t)b * PER_B;

    float acc[2][8][4];
    gemm_acc(g_wwh + 3 * 131072, g_wwl + 3 * 131072, bph, m0, n0, gsm, acc);

    const int tid = threadIdx.x, lane = tid & 31, warp = tid >> 5;
    const int wm = warp & 3, wn = warp >> 2;
    const int g = lane >> 2, tg = lane & 3;
#pragma unroll
    for (int mt = 0; mt < 2; mt++) {
        int r0 = m0 + wm * 32 + mt * 16 + g;
        float bi0 = bias[r0], bi1 = bias[r0 + 8];
#pragma unroll
        for (int nt = 0; nt < 8; nt++) {
            int cn = n0 + wn * 64 + nt * 8 + 2 * tg;
            Yb[(size_t)r0 * SP + cn]           = acc[mt][nt][0] + bi0;
            Yb[(size_t)r0 * SP + cn + 1]       = acc[mt][nt][1] + bi0;
            Yb[(size_t)(r0 + 8) * SP + cn]     = acc[mt][nt][2] + bi1;
            Yb[(size_t)(r0 + 8) * SP + cn + 1] = acc[mt][nt][3] + bi1;
        }
    }
}

// ------------------------------ attention ---------------------------------
// grid (8 qblocks of 128 rows, 8 heads, 16 b), 256 thr, 2 CTAs/SM.
// 16 key-tiles of 64. smem words:
//   Kbuf0[0..2304) stride36, Kbuf1[2304..4608)
//   Vraw0[4608..6656), Vraw1[6656..8704)
//   Vh[8704..11008) stride72
//   epilogue Os (float[128][68] = 8704 w) reuses [0..8704)
#define ATTN_SMEM (11008*4)

__device__ __forceinline__ size_t tok_off(int n, int hoff) {
    return (size_t)(n >> 1) * SP + ((n & 1) << 9) + hoff;
}

__device__ __forceinline__ void attn_ld(uint32_t sb4, size_t bbw, int hoff,
                                        int t, int tid)
{
    const int bs = t & 1;
#pragma unroll
    for (int i = 0; i < 2; i++) {
        int f = tid + i * 256;
        int r = f >> 3, q4 = (f & 7) << 2;
        size_t kw = bbw + (tok_off(t * 64 + r, hoff) >> 1) + q4;
        cpa16(sb4 + (bs * 2304 + r * 36 + q4) * 4, g_kwh + kw);
    }
    {
        int pr = tid >> 3, q = tid & 7;
        size_t vw = bbw + (size_t)(t * 32 + pr) * 512 + (hoff >> 1) + q * 4;
        uint32_t d = sb4 + (4608 + bs * 2048 + pr * 64 + q * 4) * 4;
        cpa16(d, g_vwh + vw);
        cpa16(d + 32 * 4, g_vwh + vw + 256);
    }
}

__global__ __launch_bounds__(256, 2)
void attn_kernel()
{
    extern __shared__ unsigned smem_u[];
    uint32_t sb4 = (uint32_t)__cvta_generic_to_shared(smem_u);

    const int tid = threadIdx.x, lane = tid & 31, warp = tid >> 5;
    const int g = lane >> 2, tg = lane & 3;

    const int b = blockIdx.z, h = blockIdx.y;
    const int n0 = blockIdx.x * 128;
    const size_t bbw = (size_t)b * WORDS_B;
    const int hoff = h * 64;

    // Q fragments (hi/lo); scale folded into exp
    const int r0l = warp * 16 + g, r1l = r0l + 8;
    const size_t w0 = bbw + (tok_off(n0 + r0l, hoff) >> 1);
    const size_t w1 = bbw + (tok_off(n0 + r1l, hoff) >> 1);
    unsigned qh[4][4], ql[4][4];
#pragma unroll
    for (int kc = 0; kc < 4; kc++) {
        qh[kc][0] = g_qwh[w0 + kc * 8 + tg];
        qh[kc][1] = g_qwh[w1 + kc * 8 + tg];
        qh[kc][2] = g_qwh[w0 + kc * 8 + tg + 4];
        qh[kc][3] = g_qwh[w1 + kc * 8 + tg + 4];
        ql[kc][0] = g_qwl[w0 + kc * 8 + tg];
        ql[kc][1] = g_qwl[w1 + kc * 8 + tg];
        ql[kc][2] = g_qwl[w0 + kc * 8 + tg + 4];
        ql[kc][3] = g_qwl[w1 + kc * 8 + tg + 4];
    }

    float l0 = 0.f, l1 = 0.f;
    float oa[8][4];
#pragma unroll
    for (int dt = 0; dt < 8; dt++)
#pragma unroll
        for (int i = 0; i < 4; i++) oa[dt][i] = 0.f;

    attn_ld(sb4, bbw, hoff, 0, tid);
    CP_COMMIT();

    for (int t = 0; t < 16; t++) {
        const int bs = t & 1;
        if (t < 15) {
            attn_ld(sb4, bbw, hoff, t + 1, tid);
            CP_COMMIT();
            CP_WAIT1();
        } else {
            CP_WAIT0();
        }
        __syncthreads();

        // pack V: raw (pairs along d) -> Vh (pairs along key)
        {
            const unsigned* raw = smem_u + 4608 + bs * 2048;
            int pr = tid >> 3, q = tid & 7;
            uint4 a = *reinterpret_cast<const uint4*>(raw + pr * 64 + q * 4);
            uint4 c = *reinterpret_cast<const uint4*>(raw + pr * 64 + 32 + q * 4);
            uint4 p0, p1;
            p0.x = prmtb(a.x, c.x, 0x5410); p0.y = prmtb(a.x, c.x, 0x7632);
            p0.z = prmtb(a.y, c.y, 0x5410); p0.w = prmtb(a.y, c.y, 0x7632);
            p1.x = prmtb(a.z, c.z, 0x5410); p1.y = prmtb(a.z, c.z, 0x7632);
            p1.z = prmtb(a.w, c.w, 0x5410); p1.w = prmtb(a.w, c.w, 0x7632);
            *reinterpret_cast<uint4*>(smem_u + 8704 + pr * 72 + q * 8)     = p0;
            *reinterpret_cast<uint4*>(smem_u + 8704 + pr * 72 + q * 8 + 4) = p1;
        }
        __syncthreads();

        const unsigned* Kb = smem_u + bs * 2304;
        unsigned (*Vh)[72] = reinterpret_cast<unsigned(*)[72]>(smem_u + 8704);

        // S = Q K^T (2-term passes)
        float sc[8][4];
#pragma unroll
        for (int nt = 0; nt < 8; nt++) {
            sc[nt][0] = sc[nt][1] = sc[nt][2] = sc[nt][3] = 0.f;
        }
#pragma unroll
        for (int kc = 0; kc < 4; kc++) {
            unsigned kh0[8], kh1[8];
#pragma unroll
            for (int j = 0; j < 8; j++) {
                kh0[j] = Kb[(j * 8 + g) * 36 + kc * 8 + tg];
                kh1[j] = Kb[(j * 8 + g) * 36 + kc * 8 + tg + 4];
            }
#pragma unroll
            for (int j = 0; j < 8; j++)
                mma16(sc[j], qh[kc], kh0[j], kh1[j]);
#pragma unroll
            for (int j = 0; j < 8; j++)
                mma16(sc[j], ql[kc], kh0[j], kh1[j]);
        }

        // direct exp (no max needed: |S/8| <~ 2.5, far from fp32 exp limits)
        float ps0 = 0.f, ps1 = 0.f;
#pragma unroll
        for (int nt = 0; nt < 8; nt++) {
            sc[nt][0] = __expf(sc[nt][0] * 0.125f);
            sc[nt][1] = __expf(sc[nt][1] * 0.125f);
            sc[nt][2] = __expf(sc[nt][2] * 0.125f);
            sc[nt][3] = __expf(sc[nt][3] * 0.125f);
            ps0 += sc[nt][0] + sc[nt][1];
            ps1 += sc[nt][2] + sc[nt][3];
        }
        ps0 += __shfl_xor_sync(0xffffffff, ps0, 1);
        ps0 += __shfl_xor_sync(0xffffffff, ps0, 2);
        ps1 += __shfl_xor_sync(0xffffffff, ps1, 1);
        ps1 += __shfl_xor_sync(0xffffffff, ps1, 2);
        l0 += ps0;
        l1 += ps1;

        // O += P V (P split hi/lo, V hi only)
#pragma unroll
        for (int nt2 = 0; nt2 < 4; nt2++) {
            const float* s0 = sc[2 * nt2];
            const float* s1 = sc[2 * nt2 + 1];
            unsigned pah[4], pal[4];
            split2h(s0[0], s0[1], pah[0], pal[0]);
            split2h(s0[2], s0[3], pah[1], pal[1]);
            split2h(s1[0], s1[1], pah[2], pal[2]);
            split2h(s1[2], s1[3], pah[3], pal[3]);
            unsigned vh0[8], vh1[8];
#pragma unroll
            for (int dt = 0; dt < 8; dt++) {
                vh0[dt] = Vh[nt2 * 8 + tg][dt * 8 + g];
                vh1[dt] = Vh[nt2 * 8 + tg + 4][dt * 8 + g];
            }
#pragma unroll
            for (int dt = 0; dt < 8; dt++)
                mma16(oa[dt], pah, vh0[dt], vh1[dt]);
#pragma unroll
            for (int dt = 0; dt < 8; dt++)
                mma16(oa[dt], pal, vh0[dt], vh1[dt]);
        }
        __syncthreads();
    }

    const float inv0 = 1.f / l0, inv1 = 1.f / l1;

    // O -> smem (128 rows x 64 d), pair-pack along channel (hi), store
    float (*Os)[68] = reinterpret_cast<float(*)[68]>(smem_u);
#pragma unroll
    for (int dt = 0; dt < 8; dt++) {
        Os[r0l][dt * 8 + 2 * tg]     = oa[dt][0] * inv0;
        Os[r0l][dt * 8 + 2 * tg + 1] = oa[dt][1] * inv0;
        Os[r1l][dt * 8 + 2 * tg]     = oa[dt][2] * inv1;
        Os[r1l][dt * 8 + 2 * tg + 1] = oa[dt][3] * inv1;
    }
    __syncthreads();
#pragma unroll
    for (int it = 0; it < 16; it++) {
        int f = tid + it * 256;
        int jp = f >> 7, nl = f & 127;
        g_aph[bbw + (size_t)((hoff >> 1) + jp) * 1024 + n0 + nl]
            = packh(Os[nl][2 * jp], Os[nl][2 * jp + 1]);
    }
}

// --------------------- InstanceNorm (channel pair) ------------------------
__global__ __launch_bounds__(256)
void inorm2_kernel()
{
    __shared__ float ss[8], sq[8], stats[4];
    __shared__ float sbuf[2][1024];
    const float* p = g_o1 + (size_t)blockIdx.x * 2048;
    const int tid = threadIdx.x, lane = tid & 31, warp = tid >> 5;
    const int ch = tid >> 7, i2 = tid & 127;
    const float* row = p + ch * 1024;
    float4 a = reinterpret_cast<const float4*>(row)[i2 * 2];
    float4 c = reinterpret_cast<const float4*>(row)[i2 * 2 + 1];
    float s = a.x + a.y + a.z + a.w + c.x + c.y + c.z + c.w;
    float q = a.x * a.x + a.y * a.y + a.z * a.z + a.w * a.w
            + c.x * c.x + c.y * c.y + c.z * c.z + c.w * c.w;
#pragma unroll
    for (int off = 16; off > 0; off >>= 1) {
        s += __shfl_xor_sync(0xffffffff, s, off);
        q += __shfl_xor_sync(0xffffffff, q, off);
    }
    if (lane == 0) { ss[warp] = s; sq[warp] = q; }
    __syncthreads();
    if (tid == 0 || tid == 128) {
        int base = ch * 4;
        float S = ss[base] + ss[base + 1] + ss[base + 2] + ss[base + 3];
        float Qs = sq[base] + sq[base + 1] + sq[base + 2] + sq[base + 3];
        float mean = S * (1.f / SP);
        float var = Qs * (1.f / SP) - mean * mean;
        stats[ch * 2] = mean;
        stats[ch * 2 + 1] = rsqrtf(var + 1e-5f);
    }
    __syncthreads();
    float mean = stats[ch * 2], inv = stats[ch * 2 + 1];
    float* dst = &sbuf[ch][i2 * 8];
    dst[0] = (a.x - mean) * inv; dst[1] = (a.y - mean) * inv;
    dst[2] = (a.z - mean) * inv; dst[3] = (a.w - mean) * inv;
    dst[4] = (c.x - mean) * inv; dst[5] = (c.y - mean) * inv;
    dst[6] = (c.z - mean) * inv; dst[7] = (c.w - mean) * inv;
    __syncthreads();
#pragma unroll
    for (int it = 0; it < 4; it++) {
        int sidx = tid + it * 256;
        g_oph[(size_t)blockIdx.x * 1024 + sidx] = packh(sbuf[0][sidx], sbuf[1][sidx]);
    }
}

// ---------------------------------------------------------------------------
extern "C" void kernel_launch(void* const* d_in, const int* in_sizes, int n_in,
                              void* d_out, int out_size)
{
    const float* x  = (const float*)d_in[0];
    const float* Wq = (const float*)d_in[1];
    const float* bq = (const float*)d_in[2];
    const float* Wk = (const float*)d_in[3];
    const float* bk = (const float*)d_in[4];
    const float* Wv = (const float*)d_in[5];
    const float* bv = (const float*)d_in[6];
    const float* Wo = (const float*)d_in[7];
    const float* bo = (const float*)d_in[8];

    unsigned *aph, *oph;
    float *o1;
    cudaGetSymbolAddress((void**)&aph, g_aph);
    cudaGetSymbolAddress((void**)&oph, g_oph);
    cudaGetSymbolAddress((void**)&o1,  g_o1);

    cudaFuncSetAttribute(qkv_kernel,    cudaFuncAttributeMaxDynamicSharedMemorySize, GEMM_SMEM);
    cudaFuncSetAttribute(gemm_f_kernel, cudaFuncAttributeMaxDynamicSharedMemorySize, GEMM_SMEM);
    cudaFuncSetAttribute(attn_kernel,   cudaFuncAttributeMaxDynamicSharedMemorySize, ATTN_SMEM);

    wsplit_kernel<<<2048, 256>>>(Wq, Wk, Wv, Wo);
    xsplit_kernel<<<4096, 256>>>(x);

    qkv_kernel<<<dim3(8, 12, BATCH), 256, GEMM_SMEM>>>(bq, bk, bv);

    attn_kernel<<<dim3(8, 8, BATCH), 256, ATTN_SMEM>>>();

    gemm_f_kernel<<<dim3(8, 4, BATCH), 256, GEMM_SMEM>>>(bo, aph, o1);
    inorm2_kernel<<<BATCH * 256, 256>>>();
    gemm_f_kernel<<<dim3(8, 4, BATCH), 256, GEMM_SMEM>>>(bo, oph, (float*)d_out);
}

// round 13
// speedup vs baseline: 1.6646x; 1.0341x over previous
#include <cuda_runtime.h>
#include <cuda_fp16.h>
#include <cstdint>

// ---------------------------------------------------------------------------
// B=16, C=512, S=1024, HEAD=8, D_K=64
// heads view: token n -> channel n>>1, feature j=h*64+d -> spatial ((n&1)<<9)+j
// FP16 2-term compensated: A*B ~= (Ah+Al)*Bh  (error = B fp16-rounding ~2^-12)
// A-side (W, Q, P) split hi/lo fp16; B-side (X, K, V, att, o1) fp16 hi only.
// cp.async 2-stage pipelines; K tile XOR-swizzled (conflict-free LDS);
// V pre-packed once into pairs-along-key layout; max-free softmax.
// ---------------------------------------------------------------------------
#define BATCH   16
#define CH      512
#define SP      1024
#define PER_B   (CH*SP)
#define WORDS_B (PER_B/2)

__device__ unsigned g_wwh[4*512*256], g_wwl[4*512*256];
__device__ unsigned g_xph[BATCH*WORDS_B];
__device__ unsigned g_qwh[BATCH*WORDS_B], g_qwl[BATCH*WORDS_B];
__device__ unsigned g_kwh[BATCH*WORDS_B];
__device__ unsigned g_vwh[BATCH*WORDS_B];
__device__ unsigned g_vph[BATCH*WORDS_B];    // V packed pairs-along-key
__device__ unsigned g_aph[BATCH*WORDS_B];
__device__ float    g_o1[BATCH*PER_B];
__device__ unsigned g_oph[BATCH*WORDS_B];

__device__ __forceinline__ unsigned packh(float a, float b) {
    unsigned r;
    asm("cvt.rn.f16x2.f32 %0, %1, %2;" : "=r"(r) : "f"(b), "f"(a));
    return r;
}
__device__ __forceinline__ void split2h(float a, float b, unsigned& hi, unsigned& lo) {
    hi = packh(a, b);
    __half2 h = *reinterpret_cast<__half2*>(&hi);
    lo = packh(a - __half2float(__low2half(h)), b - __half2float(__high2half(h)));
}
__device__ __forceinline__ unsigned prmtb(unsigned a, unsigned b, unsigned sel) {
    unsigned d;
    asm("prmt.b32 %0,%1,%2,%3;" : "=r"(d) : "r"(a), "r"(b), "r"(sel));
    return d;
}
__device__ __forceinline__ float ex2(float x) {
    float y;
    asm("ex2.approx.f32 %0, %1;" : "=f"(y) : "f"(x));
    return y;
}
__device__ __forceinline__ void mma16(float* c, const unsigned* a, unsigned b0, unsigned b1) {
    asm volatile(
        "mma.sync.aligned.m16n8k16.row.col.f32.f16.f16.f32 "
        "{%0,%1,%2,%3},{%4,%5,%6,%7},{%8,%9},{%0,%1,%2,%3};"
        : "+f"(c[0]), "+f"(c[1]), "+f"(c[2]), "+f"(c[3])
        : "r"(a[0]), "r"(a[1]), "r"(a[2]), "r"(a[3]), "r"(b0), "r"(b1));
}
__device__ __forceinline__ void cpa16(uint32_t d, const void* s) {
    asm volatile("cp.async.cg.shared.global [%0], [%1], 16;" :: "r"(d), "l"(s));
}
#define CP_COMMIT() asm volatile("cp.async.commit_group;" ::: "memory")
#define CP_WAIT1()  asm volatile("cp.async.wait_group 1;" ::: "memory")
#define CP_WAIT0()  asm volatile("cp.async.wait_group 0;" ::: "memory")

// ------------------------------ prepasses ---------------------------------
__global__ __launch_bounds__(256)
void wsplit_kernel(const float* __restrict__ Wq, const float* __restrict__ Wk,
                   const float* __restrict__ Wv, const float* __restrict__ Wo)
{
    unsigned w = blockIdx.x * 256 + threadIdx.x;
    unsigned m = w >> 17, rem = w & 131071;
    const float* src = m == 0 ? Wq : (m == 1 ? Wk : (m == 2 ? Wv : Wo));
    float2 v = reinterpret_cast<const float2*>(src)[rem];
    unsigned h, l;
    split2h(v.x, v.y, h, l);
    g_wwh[w] = h; g_wwl[w] = l;
}

__global__ __launch_bounds__(256)
void xsplit_kernel(const float* __restrict__ X)
{
    unsigned f = blockIdx.x * 256 + threadIdx.x;
    unsigned b = f >> 16;
    unsigned kp = (f >> 8) & 255;
    unsigned n4 = (f & 255) << 2;
    const float* p = X + (size_t)b * PER_B + (size_t)(2 * kp) * SP + n4;
    float4 a = *reinterpret_cast<const float4*>(p);
    float4 c = *reinterpret_cast<const float4*>(p + SP);
    uint4 h;
    h.x = packh(a.x, c.x); h.y = packh(a.y, c.y);
    h.z = packh(a.z, c.z); h.w = packh(a.w, c.w);
    *reinterpret_cast<uint4*>(g_xph + (size_t)b * WORDS_B + (size_t)kp * 1024 + n4) = h;
}

// V repack: vp[ch][2w],[2w+1] = prmt(vw[ch][w], vw[ch][256+w]) per channel
__global__ __launch_bounds__(256)
void vpack_kernel()
{
    unsigned idx = blockIdx.x * 256 + threadIdx.x;   // 2M items
    unsigned b = idx >> 17, rem = idx & 131071;
    unsigned ch = rem >> 8, w = rem & 255;
    size_t base = (size_t)b * WORDS_B + ch * 512;
    unsigned a = g_vwh[base + w], c = g_vwh[base + 256 + w];
    uint2 o;
    o.x = prmtb(a, c, 0x5410);
    o.y = prmtb(a, c, 0x7632);
    *reinterpret_cast<uint2*>(g_vph + base + 2 * w) = o;
}

// ------------------------------ GEMM core ---------------------------------
// double-buffered cp.async; 16 chunks of k=32 (16 pair-words).
// smem words: Abuf0[0..5120) (Ah s20, Al +2560), Abuf1[5120..10240),
//             Bbuf0[10240..12416) stride136, Bbuf1[12416..14592)
#define GEMM_SMEM (14592*4)

__device__ __forceinline__ void gemm_ld(uint32_t sb4, const unsigned* __restrict__ awh,
                                        const unsigned* __restrict__ awl,
                                        const unsigned* __restrict__ bph,
                                        int m0, int n0, int kp0, int bs, int tid)
{
    uint32_t abase = sb4 + bs * 5120 * 4;
#pragma unroll
    for (int i = 0; i < 2; i++) {
        int f = tid + i * 256;
        int r = f >> 2, seg = (f & 3) << 2;
        size_t src = (size_t)(m0 + r) * 256 + kp0 + seg;
        uint32_t d = abase + (r * 20 + seg) * 4;
        cpa16(d, awh + src);
        cpa16(d + 2560 * 4, awl + src);
    }
    uint32_t bbase = sb4 + (10240 + bs * 2176) * 4;
#pragma unroll
    for (int i = 0; i < 2; i++) {
        int f = tid + i * 256;
        int kp = f >> 5, seg = (f & 31) << 2;
        cpa16(bbase + (kp * 136 + seg) * 4,
              bph + (size_t)(kp0 + kp) * 1024 + n0 + seg);
    }
}

__device__ __forceinline__ void gemm_acc(
    const unsigned* __restrict__ awh, const unsigned* __restrict__ awl,
    const unsigned* __restrict__ bph, int m0, int n0, unsigned* gsm, float acc[2][8][4])
{
    const int tid = threadIdx.x, lane = tid & 31, warp = tid >> 5;
    const int wm = warp & 3, wn = warp >> 2;
    const int g = lane >> 2, tg = lane & 3;
    uint32_t sb4 = (uint32_t)__cvta_generic_to_shared(gsm);

#pragma unroll
    for (int mt = 0; mt < 2; mt++)
#pragma unroll
        for (int nt = 0; nt < 8; nt++)
#pragma unroll
            for (int i = 0; i < 4; i++) acc[mt][nt][i] = 0.f;

    gemm_ld(sb4, awh, awl, bph, m0, n0, 0, 0, tid);
    CP_COMMIT();

    for (int c = 0; c < 16; c++) {
        const int bs = c & 1;
        if (c < 15) {
            gemm_ld(sb4, awh, awl, bph, m0, n0, (c + 1) * 16, (c + 1) & 1, tid);
            CP_COMMIT();
            CP_WAIT1();
        } else {
            CP_WAIT0();
        }
        __syncthreads();

        unsigned (*Ahp)[20]  = reinterpret_cast<unsigned(*)[20]>(gsm + bs * 5120);
        unsigned (*Alp)[20]  = reinterpret_cast<unsigned(*)[20]>(gsm + bs * 5120 + 2560);
        unsigned (*Bph)[136] = reinterpret_cast<unsigned(*)[136]>(gsm + 10240 + bs * 2176);

#pragma unroll
        for (int kc = 0; kc < 2; kc++) {
            const int base = kc * 8;
            unsigned ah[2][4], al[2][4];
#pragma unroll
            for (int mt = 0; mt < 2; mt++) {
                int rm = wm * 32 + mt * 16;
                ah[mt][0] = Ahp[rm + g][base + tg];
                ah[mt][1] = Ahp[rm + g + 8][base + tg];
                ah[mt][2] = Ahp[rm + g][base + tg + 4];
                ah[mt][3] = Ahp[rm + g + 8][base + tg + 4];
                al[mt][0] = Alp[rm + g][base + tg];
                al[mt][1] = Alp[rm + g + 8][base + tg];
                al[mt][2] = Alp[rm + g][base + tg + 4];
                al[mt][3] = Alp[rm + g + 8][base + tg + 4];
            }
#pragma unroll
            for (int ntc = 0; ntc < 2; ntc++) {
                unsigned bh0[4], bh1[4];
#pragma unroll
                for (int j = 0; j < 4; j++) {
                    int cn = wn * 64 + (ntc * 4 + j) * 8;
                    bh0[j] = Bph[base + tg][cn + g];
                    bh1[j] = Bph[base + tg + 4][cn + g];
                }
#pragma unroll
                for (int j = 0; j < 4; j++) {
                    mma16(acc[0][ntc * 4 + j], ah[0], bh0[j], bh1[j]);
                    mma16(acc[1][ntc * 4 + j], ah[1], bh0[j], bh1[j]);
                }
#pragma unroll
                for (int j = 0; j < 4; j++) {
                    mma16(acc[0][ntc * 4 + j], al[0], bh0[j], bh1[j]);
                    mma16(acc[1][ntc * 4 + j], al[1], bh0[j], bh1[j]);
                }
            }
        }
        __syncthreads();
    }
}

// fused QKV: grid (8, 12, 16); y>>2 selects {Q,K,V}
__global__ __launch_bounds__(256, 2)
void qkv_kernel(const float* __restrict__ bq, const float* __restrict__ bk,
                const float* __restrict__ bv)
{
    extern __shared__ unsigned gsm[];
    const int sel = blockIdx.y >> 2;
    const int m0 = (blockIdx.y & 3) * 128;
    const int n0 = blockIdx.x * 128;
    const int b  = blockIdx.z;
    const unsigned* awh = g_wwh + sel * 131072;
    const unsigned* awl = g_wwl + sel * 131072;
    const unsigned* bph = g_xph + (size_t)b * WORDS_B;
    const float* bias = sel == 0 ? bq : (sel == 1 ? bk : bv);
    unsigned* oh = (sel == 0 ? g_qwh : (sel == 1 ? g_kwh : g_vwh)) + (size_t)b * WORDS_B;
    unsigned* ol = g_qwl + (size_t)b * WORDS_B;

    float acc[2][8][4];
    gemm_acc(awh, awl, bph, m0, n0, gsm, acc);

    const int tid = threadIdx.x, lane = tid & 31, warp = tid >> 5;
    const int wm = warp & 3, wn = warp >> 2;
    const int g = lane >> 2, tg = lane & 3;
#pragma unroll
    for (int mt = 0; mt < 2; mt++) {
        int r0 = m0 + wm * 32 + mt * 16 + g;
        float bi0 = bias[r0], bi1 = bias[r0 + 8];
#pragma unroll
        for (int nt = 0; nt < 8; nt++) {
            int cn = n0 + wn * 64 + nt * 8 + 2 * tg;
            unsigned h, l;
            split2h(acc[mt][nt][0] + bi0, acc[mt][nt][1] + bi0, h, l);
            oh[(size_t)r0 * 512 + (cn >> 1)] = h;
            if (sel == 0) ol[(size_t)r0 * 512 + (cn >> 1)] = l;
            split2h(acc[mt][nt][2] + bi1, acc[mt][nt][3] + bi1, h, l);
            oh[(size_t)(r0 + 8) * 512 + (cn >> 1)] = h;
            if (sel == 0) ol[(size_t)(r0 + 8) * 512 + (cn >> 1)] = l;
        }
    }
}

// O-conv GEMM: A = Wo hi/lo, B = pair-packed hi; float out
__global__ __launch_bounds__(256, 2)
void gemm_f_kernel(const float* __restrict__ bias,
                   const unsigned* __restrict__ bph_all, float* __restrict__ Y)
{
    extern __shared__ unsigned gsm[];
    const int m0 = blockIdx.y * 128, n0 = blockIdx.x * 128, b = blockIdx.z;
    const unsigned* bph = bph_all + (size_t)b * WORDS_B;
    float* Yb = Y + (size_t)b * PER_B;

    float acc[2][8][4];
    gemm_acc(g_wwh + 3 * 131072, g_wwl + 3 * 131072, bph, m0, n0, gsm, acc);

    const int tid = threadIdx.x, lane = tid & 31, warp = tid >> 5;
    const int wm = warp & 3, wn = warp >> 2;
    const int g = lane >> 2, tg = lane & 3;
#pragma unroll
    for (int mt = 0; mt < 2; mt++) {
        int r0 = m0 + wm * 32 + mt * 16 + g;
        float bi0 = bias[r0], bi1 = bias[r0 + 8];
#pragma unroll
        for (int nt = 0; nt < 8; nt++) {
            int cn = n0 + wn * 64 + nt * 8 + 2 * tg;
            Yb[(size_t)r0 * SP + cn]           = acc[mt][nt][0] + bi0;
            Yb[(size_t)r0 * SP + cn + 1]       = acc[mt][nt][1] + bi0;
            Yb[(size_t)(r0 + 8) * SP + cn]     = acc[mt][nt][2] + bi1;
            Yb[(size_t)(r0 + 8) * SP + cn + 1] = acc[mt][nt][3] + bi1;
        }
    }
}

// ------------------------------ attention ---------------------------------
// grid (8 qblocks of 128 rows, 8 heads, 16 b), 256 thr, 2 CTAs/SM.
// 16 key-tiles of 64. smem words:
//   Kbuf: 2 x [64][32] XOR-swizzled            [0..4096)
//   Vbuf: 2 x [32][72] pairs-along-key         [4096..8704)
//   epilogue Os float[128][68] = 8704 w reuses [0..8704)
#define ATTN_SMEM (8704*4)

__device__ __forceinline__ size_t tok_off(int n, int hoff) {
    return (size_t)(n >> 1) * SP + ((n & 1) << 9) + hoff;
}

__device__ __forceinline__ void attn_ld(uint32_t sb4, size_t bbw, int hoff,
                                        int t, int tid)
{
    const int bs = t & 1;
#pragma unroll
    for (int i = 0; i < 2; i++) {
        int f = tid + i * 256;
        int r = f >> 3, q4 = (f & 7) << 2;
        size_t kw = bbw + (tok_off(t * 64 + r, hoff) >> 1) + q4;
        uint32_t c = q4 ^ ((r & 7) << 2);       // XOR swizzle
        cpa16(sb4 + (bs * 2048 + r * 32 + c) * 4, g_kwh + kw);
    }
#pragma unroll
    for (int i = 0; i < 2; i++) {
        int f = tid + i * 256;
        int pr = f >> 4, q4 = (f & 15) << 2;
        size_t vw = bbw + (size_t)(t * 32 + pr) * 512 + hoff + q4;
        cpa16(sb4 + (4096 + bs * 2304 + pr * 72 + q4) * 4, g_vph + vw);
    }
}

__global__ __launch_bounds__(256, 2)
void attn_kernel()
{
    extern __shared__ unsigned smem_u[];
    uint32_t sb4 = (uint32_t)__cvta_generic_to_shared(smem_u);

    const int tid = threadIdx.x, lane = tid & 31, warp = tid >> 5;
    const int g = lane >> 2, tg = lane & 3;
    const unsigned ksw = g << 2;                 // K col swizzle for this lane

    const int b = blockIdx.z, h = blockIdx.y;
    const int n0 = blockIdx.x * 128;
    const size_t bbw = (size_t)b * WORDS_B;
    const int hoff = h * 64;

    // Q fragments (hi/lo); scale folded into exp
    const int r0l = warp * 16 + g, r1l = r0l + 8;
    const size_t w0 = bbw + (tok_off(n0 + r0l, hoff) >> 1);
    const size_t w1 = bbw + (tok_off(n0 + r1l, hoff) >> 1);
    unsigned qh[4][4], ql[4][4];
#pragma unroll
    for (int kc = 0; kc < 4; kc++) {
        qh[kc][0] = g_qwh[w0 + kc * 8 + tg];
        qh[kc][1] = g_qwh[w1 + kc * 8 + tg];
        qh[kc][2] = g_qwh[w0 + kc * 8 + tg + 4];
        qh[kc][3] = g_qwh[w1 + kc * 8 + tg + 4];
        ql[kc][0] = g_qwl[w0 + kc * 8 + tg];
        ql[kc][1] = g_qwl[w1 + kc * 8 + tg];
        ql[kc][2] = g_qwl[w0 + kc * 8 + tg + 4];
        ql[kc][3] = g_qwl[w1 + kc * 8 + tg + 4];
    }

    float l0 = 0.f, l1 = 0.f;
    float oa[8][4];
#pragma unroll
    for (int dt = 0; dt < 8; dt++)
#pragma unroll
        for (int i = 0; i < 4; i++) oa[dt][i] = 0.f;

    attn_ld(sb4, bbw, hoff, 0, tid);
    CP_COMMIT();

    const float C = 0.18033688011f;              // 0.125 * log2(e)

    for (int t = 0; t < 16; t++) {
        const int bs = t & 1;
        if (t < 15) {
            attn_ld(sb4, bbw, hoff, t + 1, tid);
            CP_COMMIT();
            CP_WAIT1();
        } else {
            CP_WAIT0();
        }
        __syncthreads();

        const unsigned* Kb = smem_u + bs * 2048;
        unsigned (*Vh)[72] = reinterpret_cast<unsigned(*)[72]>(smem_u + 4096 + bs * 2304);

        // S = Q K^T (2-term passes), swizzled conflict-free K reads
        float sc[8][4];
#pragma unroll
        for (int nt = 0; nt < 8; nt++) {
            sc[nt][0] = sc[nt][1] = sc[nt][2] = sc[nt][3] = 0.f;
        }
#pragma unroll
        for (int kc = 0; kc < 4; kc++) {
            unsigned kh0[8], kh1[8];
#pragma unroll
            for (int j = 0; j < 8; j++) {
                const unsigned rb = (j * 8 + g) * 32;
                kh0[j] = Kb[rb + ((kc * 8 + tg) ^ ksw)];
                kh1[j] = Kb[rb + ((kc * 8 + tg + 4) ^ ksw)];
            }
#pragma unroll
            for (int j = 0; j < 8; j++)
                mma16(sc[j], qh[kc], kh0[j], kh1[j]);
#pragma unroll
            for (int j = 0; j < 8; j++)
                mma16(sc[j], ql[kc], kh0[j], kh1[j]);
        }

        // direct exp2 (no running max needed; |S|*C << fp32 range)
        float ps0 = 0.f, ps1 = 0.f;
#pragma unroll
        for (int nt = 0; nt < 8; nt++) {
            sc[nt][0] = ex2(sc[nt][0] * C);
            sc[nt][1] = ex2(sc[nt][1] * C);
            sc[nt][2] = ex2(sc[nt][2] * C);
            sc[nt][3] = ex2(sc[nt][3] * C);
            ps0 += sc[nt][0] + sc[nt][1];
            ps1 += sc[nt][2] + sc[nt][3];
        }
        ps0 += __shfl_xor_sync(0xffffffff, ps0, 1);
        ps0 += __shfl_xor_sync(0xffffffff, ps0, 2);
        ps1 += __shfl_xor_sync(0xffffffff, ps1, 1);
        ps1 += __shfl_xor_sync(0xffffffff, ps1, 2);
        l0 += ps0;
        l1 += ps1;

        // O += P V (P split hi/lo, V hi only)
#pragma unroll
        for (int nt2 = 0; nt2 < 4; nt2++) {
            const float* s0 = sc[2 * nt2];
            const float* s1 = sc[2 * nt2 + 1];
            unsigned pah[4], pal[4];
            split2h(s0[0], s0[1], pah[0], pal[0]);
            split2h(s0[2], s0[3], pah[1], pal[1]);
            split2h(s1[0], s1[1], pah[2], pal[2]);
            split2h(s1[2], s1[3], pah[3], pal[3]);
            unsigned vh0[8], vh1[8];
#pragma unroll
            for (int dt = 0; dt < 8; dt++) {
                vh0[dt] = Vh[nt2 * 8 + tg][dt * 8 + g];
                vh1[dt] = Vh[nt2 * 8 + tg + 4][dt * 8 + g];
            }
#pragma unroll
            for (int dt = 0; dt < 8; dt++)
                mma16(oa[dt], pah, vh0[dt], vh1[dt]);
#pragma unroll
            for (int dt = 0; dt < 8; dt++)
                mma16(oa[dt], pal, vh0[dt], vh1[dt]);
        }
        __syncthreads();
    }

    const float inv0 = 1.f / l0, inv1 = 1.f / l1;

    // O -> smem (128 rows x 64 d), pair-pack along channel (hi), store
    float (*Os)[68] = reinterpret_cast<float(*)[68]>(smem_u);
#pragma unroll
    for (int dt = 0; dt < 8; dt++) {
        Os[r0l][dt * 8 + 2 * tg]     = oa[dt][0] * inv0;
        Os[r0l][dt * 8 + 2 * tg + 1] = oa[dt][1] * inv0;
        Os[r1l][dt * 8 + 2 * tg]     = oa[dt][2] * inv1;
        Os[r1l][dt * 8 + 2 * tg + 1] = oa[dt][3] * inv1;
    }
    __syncthreads();
#pragma unroll
    for (int it = 0; it < 16; it++) {
        int f = tid + it * 256;
        int jp = f >> 7, nl = f & 127;
        g_aph[bbw + (size_t)((hoff >> 1) + jp) * 1024 + n0 + nl]
            = packh(Os[nl][2 * jp], Os[nl][2 * jp + 1]);
    }
}

// --------------------- InstanceNorm (channel pair) ------------------------
__global__ __launch_bounds__(256)
void inorm2_kernel()
{
    __shared__ float ss[8], sq[8], stats[4];
    __shared__ float sbuf[2][1024];
    const float* p = g_o1 + (size_t)blockIdx.x * 2048;
    const int tid = threadIdx.x, lane = tid & 31, warp = tid >> 5;
    const int ch = tid >> 7, i2 = tid & 127;
    const float* row = p + ch * 1024;
    float4 a = reinterpret_cast<const float4*>(row)[i2 * 2];
    float4 c = reinterpret_cast<const float4*>(row)[i2 * 2 + 1];
    float s = a.x + a.y + a.z + a.w + c.x + c.y + c.z + c.w;
    float q = a.x * a.x + a.y * a.y + a.z * a.z + a.w * a.w
            + c.x * c.x + c.y * c.y + c.z * c.z + c.w * c.w;
#pragma unroll
    for (int off = 16; off > 0; off >>= 1) {
        s += __shfl_xor_sync(0xffffffff, s, off);
        q += __shfl_xor_sync(0xffffffff, q, off);
    }
    if (lane == 0) { ss[warp] = s; sq[warp] = q; }
    __syncthreads();
    if (tid == 0 || tid == 128) {
        int base = ch * 4;
        float S = ss[base] + ss[base + 1] + ss[base + 2] + ss[base + 3];
        float Qs = sq[base] + sq[base + 1] + sq[base + 2] + sq[base + 3];
        float mean = S * (1.f / SP);
        float var = Qs * (1.f / SP) - mean * mean;
        stats[ch * 2] = mean;
        stats[ch * 2 + 1] = rsqrtf(var + 1e-5f);
    }
    __syncthreads();
    float mean = stats[ch * 2], inv = stats[ch * 2 + 1];
    float* dst = &sbuf[ch][i2 * 8];
    dst[0] = (a.x - mean) * inv; dst[1] = (a.y - mean) * inv;
    dst[2] = (a.z - mean) * inv; dst[3] = (a.w - mean) * inv;
    dst[4] = (c.x - mean) * inv; dst[5] = (c.y - mean) * inv;
    dst[6] = (c.z - mean) * inv; dst[7] = (c.w - mean) * inv;
    __syncthreads();
#pragma unroll
    for (int it = 0; it < 4; it++) {
        int sidx = tid + it * 256;
        g_oph[(size_t)blockIdx.x * 1024 + sidx] = packh(sbuf[0][sidx], sbuf[1][sidx]);
    }
}

// ---------------------------------------------------------------------------
extern "C" void kernel_launch(void* const* d_in, const int* in_sizes, int n_in,
                              void* d_out, int out_size)
{
    const float* x  = (const float*)d_in[0];
    const float* Wq = (const float*)d_in[1];
    const float* bq = (const float*)d_in[2];
    const float* Wk = (const float*)d_in[3];
    const float* bk = (const float*)d_in[4];
    const float* Wv = (const float*)d_in[5];
    const float* bv = (const float*)d_in[6];
    const float* Wo = (const float*)d_in[7];
    const float* bo = (const float*)d_in[8];

    unsigned *aph, *oph;
    float *o1;
    cudaGetSymbolAddress((void**)&aph, g_aph);
    cudaGetSymbolAddress((void**)&oph, g_oph);
    cudaGetSymbolAddress((void**)&o1,  g_o1);

    cudaFuncSetAttribute(qkv_kernel,    cudaFuncAttributeMaxDynamicSharedMemorySize, GEMM_SMEM);
    cudaFuncSetAttribute(gemm_f_kernel, cudaFuncAttributeMaxDynamicSharedMemorySize, GEMM_SMEM);
    cudaFuncSetAttribute(attn_kernel,   cudaFuncAttributeMaxDynamicSharedMemorySize, ATTN_SMEM);

    wsplit_kernel<<<2048, 256>>>(Wq, Wk, Wv, Wo);
    xsplit_kernel<<<4096, 256>>>(x);

    qkv_kernel<<<dim3(8, 12, BATCH), 256, GEMM_SMEM>>>(bq, bk, bv);
    vpack_kernel<<<8192, 256>>>();

    attn_kernel<<<dim3(8, 8, BATCH), 256, ATTN_SMEM>>>();

    gemm_f_kernel<<<dim3(8, 4, BATCH), 256, GEMM_SMEM>>>(bo, aph, o1);
    inorm2_kernel<<<BATCH * 256, 256>>>();
    gemm_f_kernel<<<dim3(8, 4, BATCH), 256, GEMM_SMEM>>>(bo, oph, (float*)d_out);
}

// round 14
// speedup vs baseline: 1.9740x; 1.1859x over previous
#include <cuda_runtime.h>
#include <cuda_fp16.h>
#include <cstdint>

// ---------------------------------------------------------------------------
// B=16, C=512, S=1024, HEAD=8, D_K=64
// heads view: token n -> channel n>>1, feature j=h*64+d -> spatial ((n&1)<<9)+j
// FP16 compensated selectively:
//   linear path (V-proj, P*V, both O-convs): A 2-term (Ah+Al)*Bh
//   softmax-dampened path (Q-proj, K-proj, S=Q*K): 1-term Ah*Bh
// cp.async 2-stage pipelines; K tile XOR-swizzled; V pre-packed; max-free softmax.
// ---------------------------------------------------------------------------
#define BATCH   16
#define CH      512
#define SP      1024
#define PER_B   (CH*SP)
#define WORDS_B (PER_B/2)

__device__ unsigned g_wwh[4*512*256], g_wwl[4*512*256];
__device__ unsigned g_xph[BATCH*WORDS_B];
__device__ unsigned g_qwh[BATCH*WORDS_B];
__device__ unsigned g_kwh[BATCH*WORDS_B];
__device__ unsigned g_vwh[BATCH*WORDS_B];
__device__ unsigned g_vph[BATCH*WORDS_B];    // V packed pairs-along-key
__device__ unsigned g_aph[BATCH*WORDS_B];
__device__ float    g_o1[BATCH*PER_B];
__device__ unsigned g_oph[BATCH*WORDS_B];

__device__ __forceinline__ unsigned packh(float a, float b) {
    unsigned r;
    asm("cvt.rn.f16x2.f32 %0, %1, %2;" : "=r"(r) : "f"(b), "f"(a));
    return r;
}
__device__ __forceinline__ void split2h(float a, float b, unsigned& hi, unsigned& lo) {
    hi = packh(a, b);
    __half2 h = *reinterpret_cast<__half2*>(&hi);
    lo = packh(a - __half2float(__low2half(h)), b - __half2float(__high2half(h)));
}
__device__ __forceinline__ unsigned prmtb(unsigned a, unsigned b, unsigned sel) {
    unsigned d;
    asm("prmt.b32 %0,%1,%2,%3;" : "=r"(d) : "r"(a), "r"(b), "r"(sel));
    return d;
}
__device__ __forceinline__ float ex2(float x) {
    float y;
    asm("ex2.approx.f32 %0, %1;" : "=f"(y) : "f"(x));
    return y;
}
__device__ __forceinline__ void mma16(float* c, const unsigned* a, unsigned b0, unsigned b1) {
    asm volatile(
        "mma.sync.aligned.m16n8k16.row.col.f32.f16.f16.f32 "
        "{%0,%1,%2,%3},{%4,%5,%6,%7},{%8,%9},{%0,%1,%2,%3};"
        : "+f"(c[0]), "+f"(c[1]), "+f"(c[2]), "+f"(c[3])
        : "r"(a[0]), "r"(a[1]), "r"(a[2]), "r"(a[3]), "r"(b0), "r"(b1));
}
__device__ __forceinline__ void cpa16(uint32_t d, const void* s) {
    asm volatile("cp.async.cg.shared.global [%0], [%1], 16;" :: "r"(d), "l"(s));
}
#define CP_COMMIT() asm volatile("cp.async.commit_group;" ::: "memory")
#define CP_WAIT1()  asm volatile("cp.async.wait_group 1;" ::: "memory")
#define CP_WAIT0()  asm volatile("cp.async.wait_group 0;" ::: "memory")

// ------------------------------ prepasses ---------------------------------
__global__ __launch_bounds__(256)
void wsplit_kernel(const float* __restrict__ Wq, const float* __restrict__ Wk,
                   const float* __restrict__ Wv, const float* __restrict__ Wo)
{
    unsigned w = blockIdx.x * 256 + threadIdx.x;
    unsigned m = w >> 17, rem = w & 131071;
    const float* src = m == 0 ? Wq : (m == 1 ? Wk : (m == 2 ? Wv : Wo));
    float2 v = reinterpret_cast<const float2*>(src)[rem];
    unsigned h, l;
    split2h(v.x, v.y, h, l);
    g_wwh[w] = h; g_wwl[w] = l;
}

__global__ __launch_bounds__(256)
void xsplit_kernel(const float* __restrict__ X)
{
    unsigned f = blockIdx.x * 256 + threadIdx.x;
    unsigned b = f >> 16;
    unsigned kp = (f >> 8) & 255;
    unsigned n4 = (f & 255) << 2;
    const float* p = X + (size_t)b * PER_B + (size_t)(2 * kp) * SP + n4;
    float4 a = *reinterpret_cast<const float4*>(p);
    float4 c = *reinterpret_cast<const float4*>(p + SP);
    uint4 h;
    h.x = packh(a.x, c.x); h.y = packh(a.y, c.y);
    h.z = packh(a.z, c.z); h.w = packh(a.w, c.w);
    *reinterpret_cast<uint4*>(g_xph + (size_t)b * WORDS_B + (size_t)kp * 1024 + n4) = h;
}

__global__ __launch_bounds__(256)
void vpack_kernel()
{
    unsigned idx = blockIdx.x * 256 + threadIdx.x;
    unsigned b = idx >> 17, rem = idx & 131071;
    unsigned ch = rem >> 8, w = rem & 255;
    size_t base = (size_t)b * WORDS_B + ch * 512;
    unsigned a = g_vwh[base + w], c = g_vwh[base + 256 + w];
    uint2 o;
    o.x = prmtb(a, c, 0x5410);
    o.y = prmtb(a, c, 0x7632);
    *reinterpret_cast<uint2*>(g_vph + base + 2 * w) = o;
}

// ------------------------------ GEMM core ---------------------------------
// TERMS=2: acc += (Ah+Al)*Bh ; TERMS=1: acc += Ah*Bh
// smem words: Abuf0[0..5120) (Ah s20, Al +2560), Abuf1[5120..10240),
//             Bbuf0[10240..12416) stride136, Bbuf1[12416..14592)
#define GEMM_SMEM (14592*4)

template<int TERMS>
__device__ __forceinline__ void gemm_ld(uint32_t sb4, const unsigned* __restrict__ awh,
                                        const unsigned* __restrict__ awl,
                                        const unsigned* __restrict__ bph,
                                        int m0, int n0, int kp0, int bs, int tid)
{
    uint32_t abase = sb4 + bs * 5120 * 4;
#pragma unroll
    for (int i = 0; i < 2; i++) {
        int f = tid + i * 256;
        int r = f >> 2, seg = (f & 3) << 2;
        size_t src = (size_t)(m0 + r) * 256 + kp0 + seg;
        uint32_t d = abase + (r * 20 + seg) * 4;
        cpa16(d, awh + src);
        if (TERMS == 2) cpa16(d + 2560 * 4, awl + src);
    }
    uint32_t bbase = sb4 + (10240 + bs * 2176) * 4;
#pragma unroll
    for (int i = 0; i < 2; i++) {
        int f = tid + i * 256;
        int kp = f >> 5, seg = (f & 31) << 2;
        cpa16(bbase + (kp * 136 + seg) * 4,
              bph + (size_t)(kp0 + kp) * 1024 + n0 + seg);
    }
}

template<int TERMS>
__device__ __forceinline__ void gemm_acc(
    const unsigned* __restrict__ awh, const unsigned* __restrict__ awl,
    const unsigned* __restrict__ bph, int m0, int n0, unsigned* gsm, float acc[2][8][4])
{
    const int tid = threadIdx.x, lane = tid & 31, warp = tid >> 5;
    const int wm = warp & 3, wn = warp >> 2;
    const int g = lane >> 2, tg = lane & 3;
    uint32_t sb4 = (uint32_t)__cvta_generic_to_shared(gsm);

#pragma unroll
    for (int mt = 0; mt < 2; mt++)
#pragma unroll
        for (int nt = 0; nt < 8; nt++)
#pragma unroll
            for (int i = 0; i < 4; i++) acc[mt][nt][i] = 0.f;

    gemm_ld<TERMS>(sb4, awh, awl, bph, m0, n0, 0, 0, tid);
    CP_COMMIT();

    for (int c = 0; c < 16; c++) {
        const int bs = c & 1;
        if (c < 15) {
            gemm_ld<TERMS>(sb4, awh, awl, bph, m0, n0, (c + 1) * 16, (c + 1) & 1, tid);
            CP_COMMIT();
            CP_WAIT1();
        } else {
            CP_WAIT0();
        }
        __syncthreads();

        unsigned (*Ahp)[20]  = reinterpret_cast<unsigned(*)[20]>(gsm + bs * 5120);
        unsigned (*Alp)[20]  = reinterpret_cast<unsigned(*)[20]>(gsm + bs * 5120 + 2560);
        unsigned (*Bph)[136] = reinterpret_cast<unsigned(*)[136]>(gsm + 10240 + bs * 2176);

#pragma unroll
        for (int kc = 0; kc < 2; kc++) {
            const int base = kc * 8;
            unsigned ah[2][4], al[2][4];
#pragma unroll
            for (int mt = 0; mt < 2; mt++) {
                int rm = wm * 32 + mt * 16;
                ah[mt][0] = Ahp[rm + g][base + tg];
                ah[mt][1] = Ahp[rm + g + 8][base + tg];
                ah[mt][2] = Ahp[rm + g][base + tg + 4];
                ah[mt][3] = Ahp[rm + g + 8][base + tg + 4];
                if (TERMS == 2) {
                    al[mt][0] = Alp[rm + g][base + tg];
                    al[mt][1] = Alp[rm + g + 8][base + tg];
                    al[mt][2] = Alp[rm + g][base + tg + 4];
                    al[mt][3] = Alp[rm + g + 8][base + tg + 4];
                }
            }
#pragma unroll
            for (int ntc = 0; ntc < 2; ntc++) {
                unsigned bh0[4], bh1[4];
#pragma unroll
                for (int j = 0; j < 4; j++) {
                    int cn = wn * 64 + (ntc * 4 + j) * 8;
                    bh0[j] = Bph[base + tg][cn + g];
                    bh1[j] = Bph[base + tg + 4][cn + g];
                }
#pragma unroll
                for (int j = 0; j < 4; j++) {
                    mma16(acc[0][ntc * 4 + j], ah[0], bh0[j], bh1[j]);
                    mma16(acc[1][ntc * 4 + j], ah[1], bh0[j], bh1[j]);
                }
                if (TERMS == 2) {
#pragma unroll
                    for (int j = 0; j < 4; j++) {
                        mma16(acc[0][ntc * 4 + j], al[0], bh0[j], bh1[j]);
                        mma16(acc[1][ntc * 4 + j], al[1], bh0[j], bh1[j]);
                    }
                }
            }
        }
        __syncthreads();
    }
}

// fused QKV: grid (8, 12, 16); y>>2 selects {Q,K,V}; Q/K 1-term, V 2-term
__global__ __launch_bounds__(256, 2)
void qkv_kernel(const float* __restrict__ bq, const float* __restrict__ bk,
                const float* __restrict__ bv)
{
    extern __shared__ unsigned gsm[];
    const int sel = blockIdx.y >> 2;
    const int m0 = (blockIdx.y & 3) * 128;
    const int n0 = blockIdx.x * 128;
    const int b  = blockIdx.z;
    const unsigned* awh = g_wwh + sel * 131072;
    const unsigned* awl = g_wwl + sel * 131072;
    const unsigned* bph = g_xph + (size_t)b * WORDS_B;
    const float* bias = sel == 0 ? bq : (sel == 1 ? bk : bv);
    unsigned* oh = (sel == 0 ? g_qwh : (sel == 1 ? g_kwh : g_vwh)) + (size_t)b * WORDS_B;

    float acc[2][8][4];
    if (sel == 2) gemm_acc<2>(awh, awl, bph, m0, n0, gsm, acc);
    else          gemm_acc<1>(awh, awl, bph, m0, n0, gsm, acc);

    const int tid = threadIdx.x, lane = tid & 31, warp = tid >> 5;
    const int wm = warp & 3, wn = warp >> 2;
    const int g = lane >> 2, tg = lane & 3;
#pragma unroll
    for (int mt = 0; mt < 2; mt++) {
        int r0 = m0 + wm * 32 + mt * 16 + g;
        float bi0 = bias[r0], bi1 = bias[r0 + 8];
#pragma unroll
        for (int nt = 0; nt < 8; nt++) {
            int cn = n0 + wn * 64 + nt * 8 + 2 * tg;
            oh[(size_t)r0 * 512 + (cn >> 1)] =
                packh(acc[mt][nt][0] + bi0, acc[mt][nt][1] + bi0);
            oh[(size_t)(r0 + 8) * 512 + (cn >> 1)] =
                packh(acc[mt][nt][2] + bi1, acc[mt][nt][3] + bi1);
        }
    }
}

// O-conv GEMM: A = Wo hi/lo (2-term), B = pair-packed hi; float out
__global__ __launch_bounds__(256, 2)
void gemm_f_kernel(const float* __restrict__ bias,
                   const unsigned* __restrict__ bph_all, float* __restrict__ Y)
{
    extern __shared__ unsigned gsm[];
    const int m0 = blockIdx.y * 128, n0 = blockIdx.x * 128, b = blockIdx.z;
    const unsigned* bph = bph_all + (size_t)b * WORDS_B;
    float* Yb = Y + (size_t)b * PER_B;

    float acc[2][8][4];
    gemm_acc<2>(g_wwh + 3 * 131072, g_wwl + 3 * 131072, bph, m0, n0, gsm, acc);

    const int tid = threadIdx.x, lane = tid & 31, warp = tid >> 5;
    const int wm = warp & 3, wn = warp >> 2;
    const int g = lane >> 2, tg = lane & 3;
#pragma unroll
    for (int mt = 0; mt < 2; mt++) {
        int r0 = m0 + wm * 32 + mt * 16 + g;
        float bi0 = bias[r0], bi1 = bias[r0 + 8];
#pragma unroll
        for (int nt = 0; nt < 8; nt++) {
            int cn = n0 + wn * 64 + nt * 8 + 2 * tg;
            Yb[(size_t)r0 * SP + cn]           = acc[mt][nt][0] + bi0;
            Yb[(size_t)r0 * SP + cn + 1]       = acc[mt][nt][1] + bi0;
            Yb[(size_t)(r0 + 8) * SP + cn]     = acc[mt][nt][2] + bi1;
            Yb[(size_t)(r0 + 8) * SP + cn + 1] = acc[mt][nt][3] + bi1;
        }
    }
}

// ------------------------------ attention ---------------------------------
// grid (8 qblocks of 128 rows, 8 heads, 16 b), 256 thr, 2 CTAs/SM.
// S = Qh*Kh (1-term); P*V 2-term (P split). 16 key-tiles of 64.
// smem words: Kbuf 2x[64][32] swizzled [0..4096), Vbuf 2x[32][72] [4096..8704)
// epilogue Os float[128][68] = 8704 w reuses [0..8704)
#define ATTN_SMEM (8704*4)

__device__ __forceinline__ size_t tok_off(int n, int hoff) {
    return (size_t)(n >> 1) * SP + ((n & 1) << 9) + hoff;
}

__device__ __forceinline__ void attn_ld(uint32_t sb4, size_t bbw, int hoff,
                                        int t, int tid)
{
    const int bs = t & 1;
#pragma unroll
    for (int i = 0; i < 2; i++) {
        int f = tid + i * 256;
        int r = f >> 3, q4 = (f & 7) << 2;
        size_t kw = bbw + (tok_off(t * 64 + r, hoff) >> 1) + q4;
        uint32_t c = q4 ^ ((r & 7) << 2);
        cpa16(sb4 + (bs * 2048 + r * 32 + c) * 4, g_kwh + kw);
    }
#pragma unroll
    for (int i = 0; i < 2; i++) {
        int f = tid + i * 256;
        int pr = f >> 4, q4 = (f & 15) << 2;
        size_t vw = bbw + (size_t)(t * 32 + pr) * 512 + hoff + q4;
        cpa16(sb4 + (4096 + bs * 2304 + pr * 72 + q4) * 4, g_vph + vw);
    }
}

__global__ __launch_bounds__(256, 2)
void attn_kernel()
{
    extern __shared__ unsigned smem_u[];
    uint32_t sb4 = (uint32_t)__cvta_generic_to_shared(smem_u);

    const int tid = threadIdx.x, lane = tid & 31, warp = tid >> 5;
    const int g = lane >> 2, tg = lane & 3;
    const unsigned ksw = g << 2;

    const int b = blockIdx.z, h = blockIdx.y;
    const int n0 = blockIdx.x * 128;
    const size_t bbw = (size_t)b * WORDS_B;
    const int hoff = h * 64;

    // Q fragments, hi only (S errors are softmax-dampened)
    const int r0l = warp * 16 + g, r1l = r0l + 8;
    const size_t w0 = bbw + (tok_off(n0 + r0l, hoff) >> 1);
    const size_t w1 = bbw + (tok_off(n0 + r1l, hoff) >> 1);
    unsigned qh[4][4];
#pragma unroll
    for (int kc = 0; kc < 4; kc++) {
        qh[kc][0] = g_qwh[w0 + kc * 8 + tg];
        qh[kc][1] = g_qwh[w1 + kc * 8 + tg];
        qh[kc][2] = g_qwh[w0 + kc * 8 + tg + 4];
        qh[kc][3] = g_qwh[w1 + kc * 8 + tg + 4];
    }

    float l0 = 0.f, l1 = 0.f;
    float oa[8][4];
#pragma unroll
    for (int dt = 0; dt < 8; dt++)
#pragma unroll
        for (int i = 0; i < 4; i++) oa[dt][i] = 0.f;

    attn_ld(sb4, bbw, hoff, 0, tid);
    CP_COMMIT();

    const float C = 0.18033688011f;              // 0.125 * log2(e)

    for (int t = 0; t < 16; t++) {
        const int bs = t & 1;
        if (t < 15) {
            attn_ld(sb4, bbw, hoff, t + 1, tid);
            CP_COMMIT();
            CP_WAIT1();
        } else {
            CP_WAIT0();
        }
        __syncthreads();

        const unsigned* Kb = smem_u + bs * 2048;
        unsigned (*Vh)[72] = reinterpret_cast<unsigned(*)[72]>(smem_u + 4096 + bs * 2304);

        // S = Qh Kh^T (single pass)
        float sc[8][4];
#pragma unroll
        for (int nt = 0; nt < 8; nt++) {
            sc[nt][0] = sc[nt][1] = sc[nt][2] = sc[nt][3] = 0.f;
        }
#pragma unroll
        for (int kc = 0; kc < 4; kc++) {
            unsigned kh0[8], kh1[8];
#pragma unroll
            for (int j = 0; j < 8; j++) {
                const unsigned rb = (j * 8 + g) * 32;
                kh0[j] = Kb[rb + ((kc * 8 + tg) ^ ksw)];
                kh1[j] = Kb[rb + ((kc * 8 + tg + 4) ^ ksw)];
            }
#pragma unroll
            for (int j = 0; j < 8; j++)
                mma16(sc[j], qh[kc], kh0[j], kh1[j]);
        }

        // direct exp2 (max-free; |S|*C << fp32 range)
        float ps0 = 0.f, ps1 = 0.f;
#pragma unroll
        for (int nt = 0; nt < 8; nt++) {
            sc[nt][0] = ex2(sc[nt][0] * C);
            sc[nt][1] = ex2(sc[nt][1] * C);
            sc[nt][2] = ex2(sc[nt][2] * C);
            sc[nt][3] = ex2(sc[nt][3] * C);
            ps0 += sc[nt][0] + sc[nt][1];
            ps1 += sc[nt][2] + sc[nt][3];
        }
        ps0 += __shfl_xor_sync(0xffffffff, ps0, 1);
        ps0 += __shfl_xor_sync(0xffffffff, ps0, 2);
        ps1 += __shfl_xor_sync(0xffffffff, ps1, 1);
        ps1 += __shfl_xor_sync(0xffffffff, ps1, 2);
        l0 += ps0;
        l1 += ps1;

        // O += P V (P split hi/lo, V hi only)
#pragma unroll
        for (int nt2 = 0; nt2 < 4; nt2++) {
            const float* s0 = sc[2 * nt2];
            const float* s1 = sc[2 * nt2 + 1];
            unsigned pah[4], pal[4];
            split2h(s0[0], s0[1], pah[0], pal[0]);
            split2h(s0[2], s0[3], pah[1], pal[1]);
            split2h(s1[0], s1[1], pah[2], pal[2]);
            split2h(s1[2], s1[3], pah[3], pal[3]);
            unsigned vh0[8], vh1[8];
#pragma unroll
            for (int dt = 0; dt < 8; dt++) {
                vh0[dt] = Vh[nt2 * 8 + tg][dt * 8 + g];
                vh1[dt] = Vh[nt2 * 8 + tg + 4][dt * 8 + g];
            }
#pragma unroll
            for (int dt = 0; dt < 8; dt++)
                mma16(oa[dt], pah, vh0[dt], vh1[dt]);
#pragma unroll
            for (int dt = 0; dt < 8; dt++)
                mma16(oa[dt], pal, vh0[dt], vh1[dt]);
        }
        __syncthreads();
    }

    const float inv0 = 1.f / l0, inv1 = 1.f / l1;

    float (*Os)[68] = reinterpret_cast<float(*)[68]>(smem_u);
#pragma unroll
    for (int dt = 0; dt < 8; dt++) {
        Os[r0l][dt * 8 + 2 * tg]     = oa[dt][0] * inv0;
        Os[r0l][dt * 8 + 2 * tg + 1] = oa[dt][1] * inv0;
        Os[r1l][dt * 8 + 2 * tg]     = oa[dt][2] * inv1;
        Os[r1l][dt * 8 + 2 * tg + 1] = oa[dt][3] * inv1;
    }
    __syncthreads();
#pragma unroll
    for (int it = 0; it < 16; it++) {
        int f = tid + it * 256;
        int jp = f >> 7, nl = f & 127;
        g_aph[bbw + (size_t)((hoff >> 1) + jp) * 1024 + n0 + nl]
            = packh(Os[nl][2 * jp], Os[nl][2 * jp + 1]);
    }
}

// --------------------- InstanceNorm (channel pair) ------------------------
__global__ __launch_bounds__(256)
void inorm2_kernel()
{
    __shared__ float ss[8], sq[8], stats[4];
    __shared__ float sbuf[2][1024];
    const float* p = g_o1 + (size_t)blockIdx.x * 2048;
    const int tid = threadIdx.x, lane = tid & 31, warp = tid >> 5;
    const int ch = tid >> 7, i2 = tid & 127;
    const float* row = p + ch * 1024;
    float4 a = reinterpret_cast<const float4*>(row)[i2 * 2];
    float4 c = reinterpret_cast<const float4*>(row)[i2 * 2 + 1];
    float s = a.x + a.y + a.z + a.w + c.x + c.y + c.z + c.w;
    float q = a.x * a.x + a.y * a.y + a.z * a.z + a.w * a.w
            + c.x * c.x + c.y * c.y + c.z * c.z + c.w * c.w;
#pragma unroll
    for (int off = 16; off > 0; off >>= 1) {
        s += __shfl_xor_sync(0xffffffff, s, off);
        q += __shfl_xor_sync(0xffffffff, q, off);
    }
    if (lane == 0) { ss[warp] = s; sq[warp] = q; }
    __syncthreads();
    if (tid == 0 || tid == 128) {
        int base = ch * 4;
        float S = ss[base] + ss[base + 1] + ss[base + 2] + ss[base + 3];
        float Qs = sq[base] + sq[base + 1] + sq[base + 2] + sq[base + 3];
        float mean = S * (1.f / SP);
        float var = Qs * (1.f / SP) - mean * mean;
        stats[ch * 2] = mean;
        stats[ch * 2 + 1] = rsqrtf(var + 1e-5f);
    }
    __syncthreads();
    float mean = stats[ch * 2], inv = stats[ch * 2 + 1];
    float* dst = &sbuf[ch][i2 * 8];
    dst[0] = (a.x - mean) * inv; dst[1] = (a.y - mean) * inv;
    dst[2] = (a.z - mean) * inv; dst[3] = (a.w - mean) * inv;
    dst[4] = (c.x - mean) * inv; dst[5] = (c.y - mean) * inv;
    dst[6] = (c.z - mean) * inv; dst[7] = (c.w - mean) * inv;
    __syncthreads();
#pragma unroll
    for (int it = 0; it < 4; it++) {
        int sidx = tid + it * 256;
        g_oph[(size_t)blockIdx.x * 1024 + sidx] = packh(sbuf[0][sidx], sbuf[1][sidx]);
    }
}

// ---------------------------------------------------------------------------
extern "C" void kernel_launch(void* const* d_in, const int* in_sizes, int n_in,
                              void* d_out, int out_size)
{
    const float* x  = (const float*)d_in[0];
    const float* Wq = (const float*)d_in[1];
    const float* bq = (const float*)d_in[2];
    const float* Wk = (const float*)d_in[3];
    const float* bk = (const float*)d_in[4];
    const float* Wv = (const float*)d_in[5];
    const float* bv = (const float*)d_in[6];
    const float* Wo = (const float*)d_in[7];
    const float* bo = (const float*)d_in[8];

    unsigned *aph, *oph;
    float *o1;
    cudaGetSymbolAddress((void**)&aph, g_aph);
    cudaGetSymbolAddress((void**)&oph, g_oph);
    cudaGetSymbolAddress((void**)&o1,  g_o1);

    cudaFuncSetAttribute(qkv_kernel,    cudaFuncAttributeMaxDynamicSharedMemorySize, GEMM_SMEM);
    cudaFuncSetAttribute(gemm_f_kernel, cudaFuncAttributeMaxDynamicSharedMemorySize, GEMM_SMEM);
    cudaFuncSetAttribute(attn_kernel,   cudaFuncAttributeMaxDynamicSharedMemorySize, ATTN_SMEM);

    wsplit_kernel<<<2048, 256>>>(Wq, Wk, Wv, Wo);
    xsplit_kernel<<<4096, 256>>>(x);

    qkv_kernel<<<dim3(8, 12, BATCH), 256, GEMM_SMEM>>>(bq, bk, bv);
    vpack_kernel<<<8192, 256>>>();

    attn_kernel<<<dim3(8, 8, BATCH), 256, ATTN_SMEM>>>();

    gemm_f_kernel<<<dim3(8, 4, BATCH), 256, GEMM_SMEM>>>(bo, aph, o1);
    inorm2_kernel<<<BATCH * 256, 256>>>();
    gemm_f_kernel<<<dim3(8, 4, BATCH), 256, GEMM_SMEM>>>(bo, oph, (float*)d_out);
}